// round 1
// baseline (speedup 1.0000x reference)
#include <cuda_runtime.h>
#include <math.h>

// ---------------------------------------------------------------------------
// WindowAttention3D fused kernel, fp32 SIMT baseline.
// B=128, T=6, H=W=8 (HW=64), N=384, DIM=192, NH=6, HD=32.
// ---------------------------------------------------------------------------

#define NB    128
#define TT    6
#define HWN   64
#define NTOK  384
#define DIMC  192
#define NHEAD 6
#define HDIM  32
#define NROWS 49152   // NB * NTOK

// scratch (device globals: allocation-free)
__device__ float g_Q[NB * NHEAD * TT * HWN * HDIM];
__device__ float g_K[NB * NHEAD * TT * HWN * HDIM];
__device__ float g_V[NB * NHEAD * TT * HWN * HDIM];
__device__ float g_pos[HWN * DIMC];

// ---------------------------------------------------------------------------
// Kernel 1: sine positional encoding (64 x 192)
// ---------------------------------------------------------------------------
__global__ void pos_kernel() {
    int idx = blockIdx.x * blockDim.x + threadIdx.x;
    if (idx >= HWN * DIMC) return;
    int hw = idx / DIMC, c = idx % DIMC;
    int row = hw >> 3, col = hw & 7;
    const float two_pi = 6.2831853071795864769f;
    const float inv_denom = two_pi / (8.0f + 1e-6f);
    int m;
    float embed;
    if (c < 96) { m = c >> 1;        embed = (float)(row + 1) * inv_denom; }
    else        { m = (c - 96) >> 1; embed = (float)(col + 1) * inv_denom; }
    float freq = powf(10000.0f, (float)m * (1.0f / 48.0f));
    float v = embed / freq;
    g_pos[idx] = (c & 1) ? cosf(v) : sinf(v);
}

// ---------------------------------------------------------------------------
// Kernel 2: qkv = (x + pos) @ Wqkv^T, scattered into g_Q/g_K/g_V
// layout [b][h][t][hw][d]; q pre-scaled by HD^-0.5.
// grid (768, 9), 256 threads, 64x64 tile, 4x4 per thread.
// ---------------------------------------------------------------------------
__global__ __launch_bounds__(256) void qkv_kernel(const float* __restrict__ x,
                                                  const float* __restrict__ Wqkv) {
    __shared__ float As[64 * 36];
    __shared__ float Bs[64 * 33];
    int tid = threadIdx.x;
    int ty = tid >> 4, tx = tid & 15;
    int r0 = blockIdx.x * 64;
    int c0 = blockIdx.y * 64;

    float acc[4][4];
#pragma unroll
    for (int a = 0; a < 4; a++)
#pragma unroll
        for (int b = 0; b < 4; b++) acc[a][b] = 0.0f;

    for (int k0 = 0; k0 < DIMC; k0 += 32) {
#pragma unroll
        for (int q = tid; q < 512; q += 256) {
            int r = q >> 3, dk = (q & 7) * 4;
            float4 xv = *(const float4*)(x + (size_t)(r0 + r) * DIMC + k0 + dk);
            float4 pv = *(const float4*)(g_pos + r * DIMC + k0 + dk);
            float4 s;
            s.x = xv.x + pv.x; s.y = xv.y + pv.y; s.z = xv.z + pv.z; s.w = xv.w + pv.w;
            *(float4*)(As + r * 36 + dk) = s;
        }
#pragma unroll
        for (int q = tid; q < 512; q += 256) {
            int c = q >> 3, dk = (q & 7) * 4;
            float4 wv = *(const float4*)(Wqkv + (size_t)(c0 + c) * DIMC + k0 + dk);
            float* bp = Bs + c * 33 + dk;
            bp[0] = wv.x; bp[1] = wv.y; bp[2] = wv.z; bp[3] = wv.w;
        }
        __syncthreads();
#pragma unroll
        for (int kk = 0; kk < 32; kk++) {
            float a[4], b[4];
#pragma unroll
            for (int u = 0; u < 4; u++) a[u] = As[(4 * ty + u) * 36 + kk];
#pragma unroll
            for (int u = 0; u < 4; u++) b[u] = Bs[(tx + 16 * u) * 33 + kk];
#pragma unroll
            for (int i2 = 0; i2 < 4; i2++)
#pragma unroll
                for (int u = 0; u < 4; u++) acc[i2][u] += a[i2] * b[u];
        }
        __syncthreads();
    }

    const float SCALE = 0.17677669529663688f;  // 32^-0.5
#pragma unroll
    for (int ru = 0; ru < 4; ru++) {
        int gr = r0 + 4 * ty + ru;
        int bidx = gr / NTOK, n = gr % NTOK;
        int t = n >> 6, hw = n & 63;
#pragma unroll
        for (int u = 0; u < 4; u++) {
            int c = c0 + tx + 16 * u;
            int s = c / DIMC, cr = c % DIMC;
            int h = cr >> 5, d = cr & 31;
            size_t dst = ((size_t)((bidx * NHEAD + h) * TT + t) << 11) + (hw << 5) + d;
            float v = acc[ru][u];
            if (s == 0)      g_Q[dst] = v * SCALE;
            else if (s == 1) g_K[dst] = v;
            else             g_V[dst] = v;
        }
    }
}

// ---------------------------------------------------------------------------
// GEMM helper for main kernel: C(64x192) += A(64x192, smem stride 196) @ W^T
// W global row-major [192][wstride], staged per 32-k chunk in Bs[c*33+kk].
// Thread (ty,tx): rows 4*ty+ru, cols tx+16*u.
// ---------------------------------------------------------------------------
__device__ __forceinline__ void gemm_tile(const float* __restrict__ A,
                                          const float* __restrict__ Wg, int wstride,
                                          float* __restrict__ Bs,
                                          float acc[4][12], int ty, int tx, int tid) {
    for (int k0 = 0; k0 < DIMC; k0 += 32) {
#pragma unroll
        for (int q = tid; q < 1536; q += 256) {
            int c = q >> 3, dk = (q & 7) * 4;
            float4 wv = *(const float4*)(Wg + (size_t)c * wstride + k0 + dk);
            float* bp = Bs + c * 33 + dk;
            bp[0] = wv.x; bp[1] = wv.y; bp[2] = wv.z; bp[3] = wv.w;
        }
        __syncthreads();
#pragma unroll
        for (int kk = 0; kk < 32; kk++) {
            float a[4], b[12];
#pragma unroll
            for (int u = 0; u < 4; u++) a[u] = A[(4 * ty + u) * 196 + k0 + kk];
#pragma unroll
            for (int u = 0; u < 12; u++) b[u] = Bs[(tx + 16 * u) * 33 + kk];
#pragma unroll
            for (int i2 = 0; i2 < 4; i2++)
#pragma unroll
                for (int u = 0; u < 12; u++) acc[i2][u] += a[i2] * b[u];
        }
        __syncthreads();
    }
}

// ---------------------------------------------------------------------------
// Kernel 3: per-(i, b) fused attention + proj + LN + MLP + j-accumulate + out.
// grid (6, 128), 256 threads, ~194 KB dynamic smem.
// ---------------------------------------------------------------------------
__global__ __launch_bounds__(256, 1) void main_kernel(
    const float* __restrict__ x, const float* __restrict__ Wproj,
    const float* __restrict__ bproj, const float* __restrict__ gamma,
    const float* __restrict__ beta, const float* __restrict__ W1,
    const float* __restrict__ b1, const float* __restrict__ W2,
    const float* __restrict__ b2, float* __restrict__ out) {
    extern __shared__ float sm[];
    float* XPs = sm;               // 64*196
    float* Os  = sm + 12544;       // 64*196
    float* Ys  = sm + 25088;       // 64*196
    float* Us  = sm + 37632;       // union region (10880 floats)
    float* Bs  = Us;               // 192*33 = 6336
    float* Ss  = Us;               // 64*65 = 4160
    float* Qh  = Us + 4160;        // 64*36 = 2304
    float* Kh  = Us + 6464;        // 64*33 = 2112
    float* Vh  = Us + 8576;        // 64*36 = 2304

    int tid = threadIdx.x;
    int ty = tid >> 4, tx = tid & 15;
    int w = tid >> 5, lane = tid & 31;
    int i = blockIdx.x, bb = blockIdx.y;

    // ---- XP = x_flat[R] @ Wx^T + bproj (j-invariant; torch .view reinterpret) ----
    {
        size_t Rbase = (size_t)i * 8192 + (size_t)bb * 64;
#pragma unroll
        for (int q = tid; q < 64 * 48; q += 256) {
            int r = q / 48, dk = (q % 48) * 4;
            float4 v = *(const float4*)(x + (Rbase + r) * DIMC + dk);
            *(float4*)(Ys + r * 196 + dk) = v;
        }
    }
    __syncthreads();

    float accs[4][12];
#pragma unroll
    for (int a = 0; a < 4; a++)
#pragma unroll
        for (int u = 0; u < 12; u++) accs[a][u] = 0.0f;
    gemm_tile(Ys, Wproj + 192, 384, Bs, accs, ty, tx, tid);
#pragma unroll
    for (int u = 0; u < 12; u++) {
        float bias = __ldg(bproj + tx + 16 * u);
#pragma unroll
        for (int ru = 0; ru < 4; ru++)
            XPs[(4 * ty + ru) * 196 + tx + 16 * u] = accs[ru][u] + bias;
    }
    __syncthreads();

    float accF[4][12];
#pragma unroll
    for (int a = 0; a < 4; a++)
#pragma unroll
        for (int u = 0; u < 12; u++) accF[a][u] = 0.0f;

#pragma unroll 1
    for (int j = 0; j < TT; j++) {
        // ---------------- attention: Os[r][h*32+d] ----------------
#pragma unroll 1
        for (int h = 0; h < NHEAD; h++) {
            const float* Qg = g_Q + (((size_t)(bb * NHEAD + h) * TT + i) << 11);
            const float* Kg = g_K + (((size_t)(bb * NHEAD + h) * TT + j) << 11);
            const float* Vg = g_V + (((size_t)(bb * NHEAD + h) * TT + j) << 11);
#pragma unroll
            for (int q = tid; q < 512; q += 256) {
                int r = q >> 3, d = (q & 7) * 4;
                float4 qv = *(const float4*)(Qg + r * 32 + d);
                *(float4*)(Qh + r * 36 + d) = qv;
                float4 kv = *(const float4*)(Kg + r * 32 + d);
                float* kp = Kh + r * 33 + d;
                kp[0] = kv.x; kp[1] = kv.y; kp[2] = kv.z; kp[3] = kv.w;
                float4 vv = *(const float4*)(Vg + r * 32 + d);
                *(float4*)(Vh + r * 36 + d) = vv;
            }
            __syncthreads();
            // S = Qh @ Kh^T  (64x64, K=32)
            {
                float sacc[4][4];
#pragma unroll
                for (int a = 0; a < 4; a++)
#pragma unroll
                    for (int u = 0; u < 4; u++) sacc[a][u] = 0.0f;
#pragma unroll
                for (int dd = 0; dd < 32; dd++) {
                    float a[4], b[4];
#pragma unroll
                    for (int u = 0; u < 4; u++) a[u] = Qh[(4 * ty + u) * 36 + dd];
#pragma unroll
                    for (int u = 0; u < 4; u++) b[u] = Kh[(tx + 16 * u) * 33 + dd];
#pragma unroll
                    for (int i2 = 0; i2 < 4; i2++)
#pragma unroll
                        for (int u = 0; u < 4; u++) sacc[i2][u] += a[i2] * b[u];
                }
#pragma unroll
                for (int ru = 0; ru < 4; ru++)
#pragma unroll
                    for (int u = 0; u < 4; u++)
                        Ss[(4 * ty + ru) * 65 + tx + 16 * u] = sacc[ru][u];
            }
            __syncthreads();
            // softmax rows (8 per warp)
#pragma unroll
            for (int rr = 0; rr < 8; rr++) {
                int row = w * 8 + rr;
                float v0 = Ss[row * 65 + lane], v1 = Ss[row * 65 + lane + 32];
                float mx = fmaxf(v0, v1);
#pragma unroll
                for (int off = 16; off; off >>= 1)
                    mx = fmaxf(mx, __shfl_xor_sync(0xffffffffu, mx, off));
                float e0 = __expf(v0 - mx), e1 = __expf(v1 - mx);
                float s = e0 + e1;
#pragma unroll
                for (int off = 16; off; off >>= 1)
                    s += __shfl_xor_sync(0xffffffffu, s, off);
                float inv = 1.0f / s;
                Ss[row * 65 + lane] = e0 * inv;
                Ss[row * 65 + lane + 32] = e1 * inv;
            }
            __syncthreads();
            // O = P @ V  (64x32, K=64)
            {
                float oacc[4][2];
#pragma unroll
                for (int a = 0; a < 4; a++) { oacc[a][0] = 0.0f; oacc[a][1] = 0.0f; }
#pragma unroll
                for (int m = 0; m < 64; m++) {
                    float v0 = Vh[m * 36 + tx];
                    float v1 = Vh[m * 36 + tx + 16];
#pragma unroll
                    for (int u = 0; u < 4; u++) {
                        float p = Ss[(4 * ty + u) * 65 + m];
                        oacc[u][0] += p * v0;
                        oacc[u][1] += p * v1;
                    }
                }
#pragma unroll
                for (int ru = 0; ru < 4; ru++) {
                    Os[(4 * ty + ru) * 196 + h * 32 + tx] = oacc[ru][0];
                    Os[(4 * ty + ru) * 196 + h * 32 + tx + 16] = oacc[ru][1];
                }
            }
            __syncthreads();
        }

        // ---------------- y = Os @ Wo^T + XPs ----------------
#pragma unroll
        for (int a = 0; a < 4; a++)
#pragma unroll
            for (int u = 0; u < 12; u++) accs[a][u] = 0.0f;
        gemm_tile(Os, Wproj, 384, Bs, accs, ty, tx, tid);
#pragma unroll
        for (int ru = 0; ru < 4; ru++)
#pragma unroll
            for (int u = 0; u < 12; u++) {
                int idx = (4 * ty + ru) * 196 + tx + 16 * u;
                Ys[idx] = accs[ru][u] + XPs[idx];
            }
        __syncthreads();

        // ---------------- LayerNorm rows of Ys ----------------
#pragma unroll
        for (int rr = 0; rr < 8; rr++) {
            int row = w * 8 + rr;
            float s1 = 0.0f, s2 = 0.0f;
#pragma unroll
            for (int u = 0; u < 6; u++) {
                float v = Ys[row * 196 + lane + 32 * u];
                s1 += v; s2 += v * v;
            }
#pragma unroll
            for (int off = 16; off; off >>= 1) {
                s1 += __shfl_xor_sync(0xffffffffu, s1, off);
                s2 += __shfl_xor_sync(0xffffffffu, s2, off);
            }
            float mu = s1 * (1.0f / 192.0f);
            float var = s2 * (1.0f / 192.0f) - mu * mu;
            float rstd = rsqrtf(var + 1e-5f);
#pragma unroll
            for (int u = 0; u < 6; u++) {
                int c = lane + 32 * u;
                float v = Ys[row * 196 + c];
                Ys[row * 196 + c] = (v - mu) * rstd * __ldg(gamma + c) + __ldg(beta + c);
            }
        }
        __syncthreads();

        // ---------------- Os = gelu(Ys @ W1^T + b1) ----------------
#pragma unroll
        for (int a = 0; a < 4; a++)
#pragma unroll
            for (int u = 0; u < 12; u++) accs[a][u] = 0.0f;
        gemm_tile(Ys, W1, 192, Bs, accs, ty, tx, tid);
#pragma unroll
        for (int u = 0; u < 12; u++) {
            float bias = __ldg(b1 + tx + 16 * u);
#pragma unroll
            for (int ru = 0; ru < 4; ru++) {
                float hv = accs[ru][u] + bias;
                float g = 0.5f * hv * (1.0f + erff(hv * 0.70710678118654752f));
                Os[(4 * ty + ru) * 196 + tx + 16 * u] = g;
            }
        }
        __syncthreads();

        // ---------------- accF += Os @ W2^T ----------------
        gemm_tile(Os, W2, 192, Bs, accF, ty, tx, tid);
        // gemm_tile ends with __syncthreads -> safe to overwrite Us next j
    }

    // ---------------- write out: [x | x + acc/T + b2] ----------------
#pragma unroll
    for (int ru = 0; ru < 4; ru++) {
        int n = i * 64 + 4 * ty + ru;
        size_t xbase = ((size_t)bb * NTOK + n) * DIMC;
        size_t obase = ((size_t)bb * NTOK + n) * (2 * DIMC);
#pragma unroll
        for (int u = 0; u < 12; u++) {
            int c = tx + 16 * u;
            float xv = __ldg(x + xbase + c);
            out[obase + c] = xv;
            out[obase + DIMC + c] = xv + accF[ru][u] * (1.0f / 6.0f) + __ldg(b2 + c);
        }
    }
}

// ---------------------------------------------------------------------------
extern "C" void kernel_launch(void* const* d_in, const int* in_sizes, int n_in,
                              void* d_out, int out_size) {
    (void)in_sizes; (void)n_in; (void)out_size;
    const float* x     = (const float*)d_in[0];
    const float* Wqkv  = (const float*)d_in[1];
    const float* Wproj = (const float*)d_in[2];
    const float* bproj = (const float*)d_in[3];
    const float* gamma = (const float*)d_in[4];
    const float* beta  = (const float*)d_in[5];
    const float* W1    = (const float*)d_in[6];
    const float* b1    = (const float*)d_in[7];
    const float* W2    = (const float*)d_in[8];
    const float* b2    = (const float*)d_in[9];
    float* out = (float*)d_out;

    pos_kernel<<<48, 256>>>();
    qkv_kernel<<<dim3(768, 9), 256>>>(x, Wqkv);

    const int smem_bytes = 48512 * 4;  // 194048 B
    cudaFuncSetAttribute(main_kernel, cudaFuncAttributeMaxDynamicSharedMemorySize, smem_bytes);
    main_kernel<<<dim3(TT, NB), 256, smem_bytes>>>(x, Wproj, bproj, gamma, beta,
                                                   W1, b1, W2, b2, out);
}

// round 2
// speedup vs baseline: 2.2931x; 2.2931x over previous
#include <cuda_runtime.h>
#include <math.h>
#include <stdint.h>

// ---------------------------------------------------------------------------
// WindowAttention3D fused kernel, tf32 mma.sync version.
// B=128, T=6, H=W=8 (HW=64), N=384, DIM=192, NH=6, HD=32.
// ---------------------------------------------------------------------------

#define NB    128
#define TT    6
#define HWN   64
#define NTOK  384
#define DIMC  192
#define NHEAD 6
#define HDIM  32

// scratch (device globals: allocation-free)
__device__ float g_Q[NB * NHEAD * TT * HWN * HDIM];
__device__ float g_K[NB * NHEAD * TT * HWN * HDIM];
__device__ float g_V[NB * NHEAD * TT * HWN * HDIM];
__device__ float g_pos[HWN * DIMC];

// ---------------------------------------------------------------------------
__device__ __forceinline__ void mma_tf32(float* c, uint32_t a0, uint32_t a1,
                                         uint32_t a2, uint32_t a3,
                                         uint32_t b0, uint32_t b1) {
    asm volatile(
        "mma.sync.aligned.m16n8k8.row.col.f32.tf32.tf32.f32 "
        "{%0,%1,%2,%3}, {%4,%5,%6,%7}, {%8,%9}, {%0,%1,%2,%3};\n"
        : "+f"(c[0]), "+f"(c[1]), "+f"(c[2]), "+f"(c[3])
        : "r"(a0), "r"(a1), "r"(a2), "r"(a3), "r"(b0), "r"(b1));
}

// ---------------------------------------------------------------------------
// Kernel 1: sine positional encoding (64 x 192)
// ---------------------------------------------------------------------------
__global__ void pos_kernel() {
    int idx = blockIdx.x * blockDim.x + threadIdx.x;
    if (idx >= HWN * DIMC) return;
    int hw = idx / DIMC, c = idx % DIMC;
    int row = hw >> 3, col = hw & 7;
    const float two_pi = 6.2831853071795864769f;
    const float inv_denom = two_pi / (8.0f + 1e-6f);
    int m;
    float embed;
    if (c < 96) { m = c >> 1;        embed = (float)(row + 1) * inv_denom; }
    else        { m = (c - 96) >> 1; embed = (float)(col + 1) * inv_denom; }
    float freq = powf(10000.0f, (float)m * (1.0f / 48.0f));
    float v = embed / freq;
    g_pos[idx] = (c & 1) ? cosf(v) : sinf(v);
}

// ---------------------------------------------------------------------------
// Warp-mma GEMM: C[2][6][4] += A(64x192, smem stride 196) @ Wg^T
// Wg global row-major [192][wstride]. Bs = smem chunk 32 x 201.
// 8 warps: warp w tile = rows (w&1)*32..+31, cols (w>>1)*48..+47.
// Fragment (row, col): row = mr + mf*16 + (lane>>2) (+8 for c2/c3),
//                      col = nc + f*8 + 2*(lane&3) (+1 for c1/c3).
// ---------------------------------------------------------------------------
__device__ __forceinline__ void gemm_mma(const float* __restrict__ As,
                                         const float* __restrict__ Wg, int wstride,
                                         float* __restrict__ Bs,
                                         float C[2][6][4], int tid) {
    int lane = tid & 31, w = tid >> 5;
    int mr = (w & 1) * 32;
    int nc = (w >> 1) * 48;
    int qr = lane >> 2, qc = lane & 3;

#pragma unroll 1
    for (int chunk = 0; chunk < 6; chunk++) {
        int k0 = chunk * 32;
        // stage W[n][k0..k0+31] -> Bs[kl][n], stride 201 (conflict-free STS)
#pragma unroll
        for (int q = tid; q < 1536; q += 256) {
            int n = q >> 3, a = q & 7;
            float4 v = *(const float4*)(Wg + (size_t)n * wstride + k0 + a * 4);
            float* bp = Bs + (4 * a) * 201 + n;
            bp[0] = v.x; bp[201] = v.y; bp[402] = v.z; bp[603] = v.w;
        }
        __syncthreads();
#pragma unroll
        for (int ks = 0; ks < 4; ks++) {
            int kk = k0 + ks * 8;
            uint32_t a[2][4];
#pragma unroll
            for (int mf = 0; mf < 2; mf++) {
                const float* ap = As + (mr + mf * 16 + qr) * 196 + kk + qc;
                a[mf][0] = __float_as_uint(ap[0]);
                a[mf][1] = __float_as_uint(ap[8 * 196]);
                a[mf][2] = __float_as_uint(ap[4]);
                a[mf][3] = __float_as_uint(ap[8 * 196 + 4]);
            }
#pragma unroll
            for (int f = 0; f < 6; f++) {
                const float* bp = Bs + (ks * 8 + qc) * 201 + nc + f * 8 + qr;
                uint32_t b0 = __float_as_uint(bp[0]);
                uint32_t b1 = __float_as_uint(bp[4 * 201]);
                mma_tf32(C[0][f], a[0][0], a[0][1], a[0][2], a[0][3], b0, b1);
                mma_tf32(C[1][f], a[1][0], a[1][1], a[1][2], a[1][3], b0, b1);
            }
        }
        __syncthreads();
    }
}

// ---------------------------------------------------------------------------
// Kernel 2: qkv = (x + pos) @ Wqkv^T  (tf32 mma), scatter into g_Q/g_K/g_V.
// grid (768, 3): 64-row tile x one of {Q,K,V}. dyn smem = As(12544)+Bs(6432).
// ---------------------------------------------------------------------------
__global__ __launch_bounds__(256, 2) void qkv_kernel(const float* __restrict__ x,
                                                     const float* __restrict__ Wqkv) {
    extern __shared__ float sm[];
    float* As = sm;            // 64*196
    float* Bs = sm + 12544;    // 32*201

    int tid = threadIdx.x;
    int lane = tid & 31, w = tid >> 5;
    int qr = lane >> 2, qc = lane & 3;
    int r0 = blockIdx.x * 64;
    int s = blockIdx.y;

    // stage A = x + pos
#pragma unroll
    for (int q = tid; q < 3072; q += 256) {
        int r = q / 48, dk = (q % 48) * 4;
        float4 xv = *(const float4*)(x + (size_t)(r0 + r) * DIMC + dk);
        float4 pv = *(const float4*)(g_pos + r * DIMC + dk);
        float4 o;
        o.x = xv.x + pv.x; o.y = xv.y + pv.y; o.z = xv.z + pv.z; o.w = xv.w + pv.w;
        *(float4*)(As + r * 196 + dk) = o;
    }
    __syncthreads();

    float C[2][6][4];
#pragma unroll
    for (int a = 0; a < 2; a++)
#pragma unroll
        for (int f = 0; f < 6; f++)
#pragma unroll
            for (int u = 0; u < 4; u++) C[a][f][u] = 0.0f;

    gemm_mma(As, Wqkv + (size_t)s * DIMC * DIMC, DIMC, Bs, C, tid);

    float* GD = (s == 0) ? g_Q : (s == 1) ? g_K : g_V;
    const float SCALE = 0.17677669529663688f;  // 32^-0.5
    float scl = (s == 0) ? SCALE : 1.0f;

    int mr = (w & 1) * 32, nc = (w >> 1) * 48;
#pragma unroll
    for (int mf = 0; mf < 2; mf++) {
#pragma unroll
        for (int f = 0; f < 6; f++) {
            int cg = nc + f * 8 + 2 * qc;
            int h = cg >> 5, d = cg & 31;
#pragma unroll
            for (int half = 0; half < 2; half++) {
                int gr = r0 + mr + mf * 16 + qr + half * 8;
                int bidx = gr / NTOK, n = gr % NTOK;
                int t = n >> 6, hw = n & 63;
                int dst = ((bidx * NHEAD + h) * TT + t) * 2048 + hw * 32 + d;
                float2 v;
                v.x = C[mf][f][half * 2 + 0] * scl;
                v.y = C[mf][f][half * 2 + 1] * scl;
                *(float2*)(GD + dst) = v;
            }
        }
    }
}

// ---------------------------------------------------------------------------
// Kernel 3: per-(i, b) fused attention + proj + LN + MLP + j-accumulate + out.
// grid (6, 128), 256 threads, ~199 KB dynamic smem.
// ---------------------------------------------------------------------------
__global__ __launch_bounds__(256, 1) void main_kernel(
    const float* __restrict__ x, const float* __restrict__ Wproj,
    const float* __restrict__ bproj, const float* __restrict__ gamma,
    const float* __restrict__ beta, const float* __restrict__ W1,
    const float* __restrict__ b1, const float* __restrict__ W2,
    const float* __restrict__ b2, float* __restrict__ out) {
    extern __shared__ float sm[];
    float* XPs = sm;               // 64*196 = 12544
    float* Os  = sm + 12544;       // 64*196
    float* Ys  = sm + 25088;       // 64*196
    float* Us  = sm + 37632;       // union: Bs(6432) | attn arrays (12032)
    float* Bs  = Us;               // 32*201
    float* Ss  = Us;               // 64*76 = 4864
    float* Qh  = Us + 4864;        // 64*36 = 2304
    float* Kh  = Us + 7168;        // 64*36 = 2304
    float* Vh  = Us + 9472;        // 64*40 = 2560  -> end 12032

    int tid = threadIdx.x;
    int lane = tid & 31, w = tid >> 5;
    int qr = lane >> 2, qc = lane & 3;
    int i = blockIdx.x, bb = blockIdx.y;

    int mrG = (w & 1) * 32, ncG = (w >> 1) * 48;   // gemm warp tile
    int mrS = (w & 3) * 16, ncS = (w >> 2) * 32;   // S warp tile
    int ncO = (w >> 2) * 16;                       // P@V warp tile

    // ---- XP = x_flat[R] @ Wx^T + bproj (j-invariant; torch .view reinterpret) ----
    {
        size_t Rbase = (size_t)i * 8192 + (size_t)bb * 64;
#pragma unroll
        for (int q = tid; q < 3072; q += 256) {
            int r = q / 48, dk = (q % 48) * 4;
            float4 v = *(const float4*)(x + (Rbase + r) * DIMC + dk);
            *(float4*)(Ys + r * 196 + dk) = v;
        }
    }
    __syncthreads();

    float accs[2][6][4];
#pragma unroll
    for (int a = 0; a < 2; a++)
#pragma unroll
        for (int f = 0; f < 6; f++)
#pragma unroll
            for (int u = 0; u < 4; u++) accs[a][f][u] = 0.0f;
    gemm_mma(Ys, Wproj + DIMC, 2 * DIMC, Bs, accs, tid);
#pragma unroll
    for (int mf = 0; mf < 2; mf++)
#pragma unroll
        for (int f = 0; f < 6; f++) {
            int col = ncG + f * 8 + 2 * qc;
            float b0v = __ldg(bproj + col), b1v = __ldg(bproj + col + 1);
#pragma unroll
            for (int half = 0; half < 2; half++) {
                int row = mrG + mf * 16 + qr + half * 8;
                float2 v;
                v.x = accs[mf][f][half * 2 + 0] + b0v;
                v.y = accs[mf][f][half * 2 + 1] + b1v;
                *(float2*)(XPs + row * 196 + col) = v;
            }
        }
    __syncthreads();

    float accF[2][6][4];
#pragma unroll
    for (int a = 0; a < 2; a++)
#pragma unroll
        for (int f = 0; f < 6; f++)
#pragma unroll
            for (int u = 0; u < 4; u++) accF[a][f][u] = 0.0f;

#pragma unroll 1
    for (int j = 0; j < TT; j++) {
        // ---------------- attention: Os[r][h*32+d] ----------------
#pragma unroll 1
        for (int h = 0; h < NHEAD; h++) {
            const float* Qg = g_Q + (((size_t)(bb * NHEAD + h) * TT + i) << 11);
            const float* Kg = g_K + (((size_t)(bb * NHEAD + h) * TT + j) << 11);
            const float* Vg = g_V + (((size_t)(bb * NHEAD + h) * TT + j) << 11);
#pragma unroll
            for (int q = tid; q < 512; q += 256) {
                int r = q >> 3, d = (q & 7) * 4;
                *(float4*)(Qh + r * 36 + d) = *(const float4*)(Qg + r * 32 + d);
                *(float4*)(Kh + r * 36 + d) = *(const float4*)(Kg + r * 32 + d);
                *(float4*)(Vh + r * 40 + d) = *(const float4*)(Vg + r * 32 + d);
            }
            __syncthreads();

            // S = Q @ K^T  (64x64, K=32), warp tile 16x32
            {
                float Sc[4][4];
#pragma unroll
                for (int f = 0; f < 4; f++)
#pragma unroll
                    for (int u = 0; u < 4; u++) Sc[f][u] = 0.0f;
#pragma unroll
                for (int ks = 0; ks < 4; ks++) {
                    int kk = ks * 8;
                    const float* ap = Qh + (mrS + qr) * 36 + kk + qc;
                    uint32_t a0 = __float_as_uint(ap[0]);
                    uint32_t a1 = __float_as_uint(ap[8 * 36]);
                    uint32_t a2 = __float_as_uint(ap[4]);
                    uint32_t a3 = __float_as_uint(ap[8 * 36 + 4]);
#pragma unroll
                    for (int f = 0; f < 4; f++) {
                        const float* bp = Kh + (ncS + f * 8 + qr) * 36 + kk + qc;
                        uint32_t b0 = __float_as_uint(bp[0]);
                        uint32_t b1 = __float_as_uint(bp[4]);
                        mma_tf32(Sc[f], a0, a1, a2, a3, b0, b1);
                    }
                }
#pragma unroll
                for (int f = 0; f < 4; f++) {
                    int col = ncS + f * 8 + 2 * qc;
                    float2 v0; v0.x = Sc[f][0]; v0.y = Sc[f][1];
                    float2 v1; v1.x = Sc[f][2]; v1.y = Sc[f][3];
                    *(float2*)(Ss + (mrS + qr) * 76 + col) = v0;
                    *(float2*)(Ss + (mrS + qr + 8) * 76 + col) = v1;
                }
            }
            __syncthreads();

            // softmax rows (8 per warp)
#pragma unroll
            for (int rr = 0; rr < 8; rr++) {
                int row = w * 8 + rr;
                float v0 = Ss[row * 76 + lane], v1 = Ss[row * 76 + lane + 32];
                float mx = fmaxf(v0, v1);
#pragma unroll
                for (int off = 16; off; off >>= 1)
                    mx = fmaxf(mx, __shfl_xor_sync(0xffffffffu, mx, off));
                float e0 = __expf(v0 - mx), e1 = __expf(v1 - mx);
                float sv = e0 + e1;
#pragma unroll
                for (int off = 16; off; off >>= 1)
                    sv += __shfl_xor_sync(0xffffffffu, sv, off);
                float inv = 1.0f / sv;
                Ss[row * 76 + lane] = e0 * inv;
                Ss[row * 76 + lane + 32] = e1 * inv;
            }
            __syncthreads();

            // O = P @ V  (64x32, K=64), warp tile 16x16
            {
                float Oc[2][4];
#pragma unroll
                for (int f = 0; f < 2; f++)
#pragma unroll
                    for (int u = 0; u < 4; u++) Oc[f][u] = 0.0f;
#pragma unroll
                for (int ks = 0; ks < 8; ks++) {
                    int kk = ks * 8;
                    const float* ap = Ss + (mrS + qr) * 76 + kk + qc;
                    uint32_t a0 = __float_as_uint(ap[0]);
                    uint32_t a1 = __float_as_uint(ap[8 * 76]);
                    uint32_t a2 = __float_as_uint(ap[4]);
                    uint32_t a3 = __float_as_uint(ap[8 * 76 + 4]);
#pragma unroll
                    for (int f = 0; f < 2; f++) {
                        const float* bp = Vh + (kk + qc) * 40 + ncO + f * 8 + qr;
                        uint32_t b0 = __float_as_uint(bp[0]);
                        uint32_t b1 = __float_as_uint(bp[4 * 40]);
                        mma_tf32(Oc[f], a0, a1, a2, a3, b0, b1);
                    }
                }
#pragma unroll
                for (int f = 0; f < 2; f++) {
                    int col = h * 32 + ncO + f * 8 + 2 * qc;
                    float2 v0; v0.x = Oc[f][0]; v0.y = Oc[f][1];
                    float2 v1; v1.x = Oc[f][2]; v1.y = Oc[f][3];
                    *(float2*)(Os + (mrS + qr) * 196 + col) = v0;
                    *(float2*)(Os + (mrS + qr + 8) * 196 + col) = v1;
                }
            }
            __syncthreads();
        }

        // ---------------- y = Os @ Wo^T + XPs ----------------
#pragma unroll
        for (int a = 0; a < 2; a++)
#pragma unroll
            for (int f = 0; f < 6; f++)
#pragma unroll
                for (int u = 0; u < 4; u++) accs[a][f][u] = 0.0f;
        gemm_mma(Os, Wproj, 2 * DIMC, Bs, accs, tid);
#pragma unroll
        for (int mf = 0; mf < 2; mf++)
#pragma unroll
            for (int f = 0; f < 6; f++) {
                int col = ncG + f * 8 + 2 * qc;
#pragma unroll
                for (int half = 0; half < 2; half++) {
                    int row = mrG + mf * 16 + qr + half * 8;
                    float2 xp = *(const float2*)(XPs + row * 196 + col);
                    float2 v;
                    v.x = accs[mf][f][half * 2 + 0] + xp.x;
                    v.y = accs[mf][f][half * 2 + 1] + xp.y;
                    *(float2*)(Ys + row * 196 + col) = v;
                }
            }
        __syncthreads();

        // ---------------- LayerNorm rows of Ys ----------------
#pragma unroll
        for (int rr = 0; rr < 8; rr++) {
            int row = w * 8 + rr;
            float s1 = 0.0f, s2 = 0.0f;
#pragma unroll
            for (int u = 0; u < 6; u++) {
                float v = Ys[row * 196 + lane + 32 * u];
                s1 += v; s2 += v * v;
            }
#pragma unroll
            for (int off = 16; off; off >>= 1) {
                s1 += __shfl_xor_sync(0xffffffffu, s1, off);
                s2 += __shfl_xor_sync(0xffffffffu, s2, off);
            }
            float mu = s1 * (1.0f / 192.0f);
            float var = s2 * (1.0f / 192.0f) - mu * mu;
            float rstd = rsqrtf(var + 1e-5f);
#pragma unroll
            for (int u = 0; u < 6; u++) {
                int c = lane + 32 * u;
                float v = Ys[row * 196 + c];
                Ys[row * 196 + c] = (v - mu) * rstd * __ldg(gamma + c) + __ldg(beta + c);
            }
        }
        __syncthreads();

        // ---------------- Os = gelu(Ys @ W1^T + b1) ----------------
#pragma unroll
        for (int a = 0; a < 2; a++)
#pragma unroll
            for (int f = 0; f < 6; f++)
#pragma unroll
                for (int u = 0; u < 4; u++) accs[a][f][u] = 0.0f;
        gemm_mma(Ys, W1, DIMC, Bs, accs, tid);
#pragma unroll
        for (int mf = 0; mf < 2; mf++)
#pragma unroll
            for (int f = 0; f < 6; f++) {
                int col = ncG + f * 8 + 2 * qc;
                float b0v = __ldg(b1 + col), b1v = __ldg(b1 + col + 1);
#pragma unroll
                for (int half = 0; half < 2; half++) {
                    int row = mrG + mf * 16 + qr + half * 8;
                    float h0 = accs[mf][f][half * 2 + 0] + b0v;
                    float h1 = accs[mf][f][half * 2 + 1] + b1v;
                    float2 v;
                    v.x = 0.5f * h0 * (1.0f + erff(h0 * 0.70710678118654752f));
                    v.y = 0.5f * h1 * (1.0f + erff(h1 * 0.70710678118654752f));
                    *(float2*)(Os + row * 196 + col) = v;
                }
            }
        __syncthreads();

        // ---------------- accF += Os @ W2^T ----------------
        gemm_mma(Os, W2, DIMC, Bs, accF, tid);
        // gemm_mma ends with __syncthreads -> safe to reuse Us next j
    }

    // ---------------- write out: [x | x + acc/T + b2] ----------------
#pragma unroll
    for (int mf = 0; mf < 2; mf++)
#pragma unroll
        for (int f = 0; f < 6; f++) {
            int col = ncG + f * 8 + 2 * qc;
            float b20 = __ldg(b2 + col), b21 = __ldg(b2 + col + 1);
#pragma unroll
            for (int half = 0; half < 2; half++) {
                int row = mrG + mf * 16 + qr + half * 8;
                int n = i * 64 + row;
                size_t base = (size_t)bb * NTOK + n;
                float2 xv = *(const float2*)(x + base * DIMC + col);
                *(float2*)(out + base * (2 * DIMC) + col) = xv;
                float2 ov;
                ov.x = xv.x + accF[mf][f][half * 2 + 0] * (1.0f / 6.0f) + b20;
                ov.y = xv.y + accF[mf][f][half * 2 + 1] * (1.0f / 6.0f) + b21;
                *(float2*)(out + base * (2 * DIMC) + DIMC + col) = ov;
            }
        }
}

// ---------------------------------------------------------------------------
extern "C" void kernel_launch(void* const* d_in, const int* in_sizes, int n_in,
                              void* d_out, int out_size) {
    (void)in_sizes; (void)n_in; (void)out_size;
    const float* x     = (const float*)d_in[0];
    const float* Wqkv  = (const float*)d_in[1];
    const float* Wproj = (const float*)d_in[2];
    const float* bproj = (const float*)d_in[3];
    const float* gamma = (const float*)d_in[4];
    const float* beta  = (const float*)d_in[5];
    const float* W1    = (const float*)d_in[6];
    const float* b1    = (const float*)d_in[7];
    const float* W2    = (const float*)d_in[8];
    const float* b2    = (const float*)d_in[9];
    float* out = (float*)d_out;

    pos_kernel<<<48, 256>>>();

    const int qkv_smem = (12544 + 32 * 201) * 4;   // 75904 B
    cudaFuncSetAttribute(qkv_kernel, cudaFuncAttributeMaxDynamicSharedMemorySize, qkv_smem);
    qkv_kernel<<<dim3(768, 3), 256, qkv_smem>>>(x, Wqkv);

    const int main_smem = (37632 + 12032) * 4;     // 198656 B
    cudaFuncSetAttribute(main_kernel, cudaFuncAttributeMaxDynamicSharedMemorySize, main_smem);
    main_kernel<<<dim3(TT, NB), 256, main_smem>>>(x, Wproj, bproj, gamma, beta,
                                                  W1, b1, W2, b2, out);
}

// round 3
// speedup vs baseline: 4.0254x; 1.7555x over previous
#include <cuda_runtime.h>
#include <cuda_bf16.h>
#include <math.h>
#include <stdint.h>

// ---------------------------------------------------------------------------
// WindowAttention3D fused kernel, bf16 mma.m16n8k16 version.
// B=128, T=6, H=W=8 (HW=64), N=384, DIM=192, NH=6, HD=32.
// ---------------------------------------------------------------------------

#define NB    128
#define TT    6
#define HWN   64
#define NTOK  384
#define DIMC  192
#define NHEAD 6
#define HDIM  32

typedef __nv_bfloat16 bf16;

// scratch (device globals: allocation-free). Q/K: [b][h][t][hw][d]; Vt: [b][h][t][d][hw]
__device__ bf16 g_Q [NB * NHEAD * TT * HWN * HDIM];
__device__ bf16 g_K [NB * NHEAD * TT * HWN * HDIM];
__device__ bf16 g_Vt[NB * NHEAD * TT * HWN * HDIM];
__device__ float g_pos[HWN * DIMC];

// ---------------------------------------------------------------------------
__device__ __forceinline__ void mma_bf16(float* c, uint32_t a0, uint32_t a1,
                                         uint32_t a2, uint32_t a3,
                                         uint32_t b0, uint32_t b1) {
    asm volatile(
        "mma.sync.aligned.m16n8k16.row.col.f32.bf16.bf16.f32 "
        "{%0,%1,%2,%3}, {%4,%5,%6,%7}, {%8,%9}, {%0,%1,%2,%3};\n"
        : "+f"(c[0]), "+f"(c[1]), "+f"(c[2]), "+f"(c[3])
        : "r"(a0), "r"(a1), "r"(a2), "r"(a3), "r"(b0), "r"(b1));
}

__device__ __forceinline__ uint32_t packbf(float lo, float hi) {
    uint32_t r;
    asm("cvt.rn.bf16x2.f32 %0, %1, %2;" : "=r"(r) : "f"(hi), "f"(lo));
    return r;
}
__device__ __forceinline__ float2 unpackbf(uint32_t p) {
    __nv_bfloat162 b = *reinterpret_cast<__nv_bfloat162*>(&p);
    return make_float2(__bfloat162float(b.x), __bfloat162float(b.y));
}

// ---------------------------------------------------------------------------
// Kernel 1: sine positional encoding (64 x 192)
// ---------------------------------------------------------------------------
__global__ void pos_kernel() {
    int idx = blockIdx.x * blockDim.x + threadIdx.x;
    if (idx >= HWN * DIMC) return;
    int hw = idx / DIMC, c = idx % DIMC;
    int row = hw >> 3, col = hw & 7;
    const float two_pi = 6.2831853071795864769f;
    const float inv_denom = two_pi / (8.0f + 1e-6f);
    int m;
    float embed;
    if (c < 96) { m = c >> 1;        embed = (float)(row + 1) * inv_denom; }
    else        { m = (c - 96) >> 1; embed = (float)(col + 1) * inv_denom; }
    float freq = powf(10000.0f, (float)m * (1.0f / 48.0f));
    float v = embed / freq;
    g_pos[idx] = (c & 1) ? cosf(v) : sinf(v);
}

// ---------------------------------------------------------------------------
// bf16 warp-mma GEMM: C[2][6][4] += A(64x192 bf16, stride 200) @ Wg^T
// Wg fp32 global row-major [192][wstride], staged bf16 in Bs[192][72] per
// 64-wide k-chunk. 8 warps: warp tile rows (w&1)*32..+31, cols (w>>1)*48..+47.
// ---------------------------------------------------------------------------
__device__ __forceinline__ void gemm_bf16(const bf16* __restrict__ As,
                                          const float* __restrict__ Wg, int wstride,
                                          bf16* __restrict__ Bs,
                                          float C[2][6][4], int tid) {
    int lane = tid & 31, w = tid >> 5;
    int mr = (w & 1) * 32, nc = (w >> 1) * 48;
    int qr = lane >> 2, qc = lane & 3;

#pragma unroll 1
    for (int chunk = 0; chunk < 3; chunk++) {
        int k0 = chunk * 64;
        // stage 192n x 64k fp32 -> bf16, Bs[n][k] stride 72
#pragma unroll
        for (int q = tid; q < 3072; q += 256) {
            int n = q >> 4, kk = (q & 15) * 4;
            float4 v = *(const float4*)(Wg + (size_t)n * wstride + k0 + kk);
            uint2 p;
            p.x = packbf(v.x, v.y);
            p.y = packbf(v.z, v.w);
            *(uint2*)(Bs + n * 72 + kk) = p;
        }
        __syncthreads();
#pragma unroll
        for (int ks = 0; ks < 4; ks++) {
            int kk = ks * 16;
            uint32_t a[2][4];
#pragma unroll
            for (int mf = 0; mf < 2; mf++) {
                const bf16* ap = As + (mr + mf * 16 + qr) * 200 + k0 + kk + 2 * qc;
                a[mf][0] = *(const uint32_t*)(ap);
                a[mf][1] = *(const uint32_t*)(ap + 8 * 200);
                a[mf][2] = *(const uint32_t*)(ap + 8);
                a[mf][3] = *(const uint32_t*)(ap + 8 * 200 + 8);
            }
#pragma unroll
            for (int f = 0; f < 6; f++) {
                const bf16* bp = Bs + (nc + f * 8 + qr) * 72 + kk + 2 * qc;
                uint32_t b0 = *(const uint32_t*)(bp);
                uint32_t b1 = *(const uint32_t*)(bp + 8);
                mma_bf16(C[0][f], a[0][0], a[0][1], a[0][2], a[0][3], b0, b1);
                mma_bf16(C[1][f], a[1][0], a[1][1], a[1][2], a[1][3], b0, b1);
            }
        }
        __syncthreads();
    }
}

// ---------------------------------------------------------------------------
// Kernel 2: qkv = (x + pos) @ Wqkv^T  (bf16 mma), scatter into g_Q/g_K/g_Vt.
// grid (768, 3). smem: As bf16 64x200 (25600B) + Bs bf16 192x72 (27648B).
// ---------------------------------------------------------------------------
__global__ __launch_bounds__(256) void qkv_kernel(const float* __restrict__ x,
                                                  const float* __restrict__ Wqkv) {
    extern __shared__ char smc[];
    bf16* As = (bf16*)smc;              // 64*200
    bf16* Bs = (bf16*)(smc + 25600);    // 192*72

    int tid = threadIdx.x;
    int lane = tid & 31, w = tid >> 5;
    int qr = lane >> 2, qc = lane & 3;
    int r0 = blockIdx.x * 64;
    int s = blockIdx.y;

    // stage A = bf16(x + pos)
#pragma unroll
    for (int q = tid; q < 1536; q += 256) {
        int r = q / 24, c8 = (q % 24) * 8;
        float4 x0 = *(const float4*)(x + (size_t)(r0 + r) * DIMC + c8);
        float4 x1 = *(const float4*)(x + (size_t)(r0 + r) * DIMC + c8 + 4);
        float4 p0 = *(const float4*)(g_pos + r * DIMC + c8);
        float4 p1 = *(const float4*)(g_pos + r * DIMC + c8 + 4);
        uint4 o;
        o.x = packbf(x0.x + p0.x, x0.y + p0.y);
        o.y = packbf(x0.z + p0.z, x0.w + p0.w);
        o.z = packbf(x1.x + p1.x, x1.y + p1.y);
        o.w = packbf(x1.z + p1.z, x1.w + p1.w);
        *(uint4*)(As + r * 200 + c8) = o;
    }
    __syncthreads();

    float C[2][6][4];
#pragma unroll
    for (int a = 0; a < 2; a++)
#pragma unroll
        for (int f = 0; f < 6; f++)
#pragma unroll
            for (int u = 0; u < 4; u++) C[a][f][u] = 0.0f;

    gemm_bf16(As, Wqkv + (size_t)s * DIMC * DIMC, DIMC, Bs, C, tid);

    const float SCALE = 0.17677669529663688f;  // 32^-0.5
    int mr = (w & 1) * 32, nc = (w >> 1) * 48;

    if (s < 2) {
        bf16* GD = (s == 0) ? g_Q : g_K;
        float scl = (s == 0) ? SCALE : 1.0f;
#pragma unroll
        for (int mf = 0; mf < 2; mf++)
#pragma unroll
            for (int f = 0; f < 6; f++) {
                int cg = nc + f * 8 + 2 * qc;
                int h = cg >> 5, d = cg & 31;
#pragma unroll
                for (int half = 0; half < 2; half++) {
                    int gr = r0 + mr + mf * 16 + qr + half * 8;
                    int bidx = gr / NTOK, n = gr % NTOK;
                    int t = n >> 6, hw = n & 63;
                    int dst = ((bidx * NHEAD + h) * TT + t) * 2048 + hw * 32 + d;
                    *(uint32_t*)(GD + dst) =
                        packbf(C[mf][f][half * 2 + 0] * scl, C[mf][f][half * 2 + 1] * scl);
                }
            }
    } else {
        // V transposed: [b][h][t][d][hw]
#pragma unroll
        for (int mf = 0; mf < 2; mf++)
#pragma unroll
            for (int f = 0; f < 6; f++) {
                int cg = nc + f * 8 + 2 * qc;
                int h = cg >> 5, d = cg & 31;
#pragma unroll
                for (int half = 0; half < 2; half++) {
                    int gr = r0 + mr + mf * 16 + qr + half * 8;
                    int bidx = gr / NTOK, n = gr % NTOK;
                    int t = n >> 6, hw = n & 63;
                    int base = ((bidx * NHEAD + h) * TT + t) * 2048;
                    g_Vt[base + d * 64 + hw]       = __float2bfloat16(C[mf][f][half * 2 + 0]);
                    g_Vt[base + (d + 1) * 64 + hw] = __float2bfloat16(C[mf][f][half * 2 + 1]);
                }
            }
    }
}

// ---------------------------------------------------------------------------
// Kernel 3: per-(i, b) fused attention + proj + LN + MLP + j-accumulate + out.
// grid (6, 128), 256 threads, 108544 B dynamic smem -> 2 CTAs/SM.
// ---------------------------------------------------------------------------
__global__ __launch_bounds__(256, 2) void main_kernel(
    const float* __restrict__ x, const float* __restrict__ Wproj,
    const float* __restrict__ bproj, const float* __restrict__ gamma,
    const float* __restrict__ beta, const float* __restrict__ W1,
    const float* __restrict__ b1, const float* __restrict__ W2,
    const float* __restrict__ b2, float* __restrict__ out) {
    extern __shared__ char smc[];
    bf16* XPs = (bf16*)smc;                 // 64*200 = 25600 B
    bf16* Os  = (bf16*)(smc + 25600);       // 64*200
    bf16* Ys  = (bf16*)(smc + 51200);       // 64*200
    // union region @76800:
    bf16*  Bs = (bf16*)(smc + 76800);       // 192*72 = 27648 B
    bf16*  Qh = (bf16*)(smc + 76800);       // 64*40 = 5120 B
    bf16*  Kh = (bf16*)(smc + 81920);       // 64*40 = 5120 B
    bf16*  Vh = (bf16*)(smc + 87040);       // 32*72 = 4608 B
    float* Ss = (float*)(smc + 91648);      // 64*66*4 = 16896 B -> end 108544
    bf16*  Ps = (bf16*)(smc + 76800);       // 64*72 = 9216 B (aliases Qh/Kh)

    int tid = threadIdx.x;
    int lane = tid & 31, w = tid >> 5;
    int qr = lane >> 2, qc = lane & 3;
    int i = blockIdx.x, bb = blockIdx.y;

    int mrG = (w & 1) * 32, ncG = (w >> 1) * 48;   // gemm warp tile
    int mrS = (w & 3) * 16, ncS = (w >> 2) * 32;   // S warp tile
    int ncO = (w >> 2) * 16;                       // P@V warp tile

    // ---- XP = x_flat[R] @ Wx^T + bproj (j-invariant; torch .view reinterpret) ----
    {
        size_t Rbase = (size_t)i * 8192 + (size_t)bb * 64;
#pragma unroll
        for (int q = tid; q < 1536; q += 256) {
            int r = q / 24, c8 = (q % 24) * 8;
            float4 x0 = *(const float4*)(x + (Rbase + r) * DIMC + c8);
            float4 x1 = *(const float4*)(x + (Rbase + r) * DIMC + c8 + 4);
            uint4 o;
            o.x = packbf(x0.x, x0.y);
            o.y = packbf(x0.z, x0.w);
            o.z = packbf(x1.x, x1.y);
            o.w = packbf(x1.z, x1.w);
            *(uint4*)(Ys + r * 200 + c8) = o;
        }
    }
    __syncthreads();

    float accs[2][6][4];
#pragma unroll
    for (int a = 0; a < 2; a++)
#pragma unroll
        for (int f = 0; f < 6; f++)
#pragma unroll
            for (int u = 0; u < 4; u++) accs[a][f][u] = 0.0f;
    gemm_bf16(Ys, Wproj + DIMC, 2 * DIMC, Bs, accs, tid);
#pragma unroll
    for (int mf = 0; mf < 2; mf++)
#pragma unroll
        for (int f = 0; f < 6; f++) {
            int col = ncG + f * 8 + 2 * qc;
            float b0v = __ldg(bproj + col), b1v = __ldg(bproj + col + 1);
#pragma unroll
            for (int half = 0; half < 2; half++) {
                int row = mrG + mf * 16 + qr + half * 8;
                *(uint32_t*)(XPs + row * 200 + col) =
                    packbf(accs[mf][f][half * 2 + 0] + b0v, accs[mf][f][half * 2 + 1] + b1v);
            }
        }
    __syncthreads();

    float accF[2][6][4];
#pragma unroll
    for (int a = 0; a < 2; a++)
#pragma unroll
        for (int f = 0; f < 6; f++)
#pragma unroll
            for (int u = 0; u < 4; u++) accF[a][f][u] = 0.0f;

#pragma unroll 1
    for (int j = 0; j < TT; j++) {
        // ---------------- attention: Os[r][h*32+d] ----------------
#pragma unroll 1
        for (int h = 0; h < NHEAD; h++) {
            const bf16* Qg = g_Q  + ((size_t)((bb * NHEAD + h) * TT + i) << 11);
            const bf16* Kg = g_K  + ((size_t)((bb * NHEAD + h) * TT + j) << 11);
            const bf16* Vg = g_Vt + ((size_t)((bb * NHEAD + h) * TT + j) << 11);
            {
                int r = tid >> 2, c8 = (tid & 3) * 8;
                *(uint4*)(Qh + r * 40 + c8) = *(const uint4*)(Qg + r * 32 + c8);
                *(uint4*)(Kh + r * 40 + c8) = *(const uint4*)(Kg + r * 32 + c8);
                int rv = tid >> 3, cv = (tid & 7) * 8;
                *(uint4*)(Vh + rv * 72 + cv) = *(const uint4*)(Vg + rv * 64 + cv);
            }
            __syncthreads();

            // S = Q @ K^T  (64x64, K=32), warp tile 16x32
            {
                float Sc[4][4];
#pragma unroll
                for (int f = 0; f < 4; f++)
#pragma unroll
                    for (int u = 0; u < 4; u++) Sc[f][u] = 0.0f;
#pragma unroll
                for (int ks = 0; ks < 2; ks++) {
                    int kk = ks * 16;
                    const bf16* ap = Qh + (mrS + qr) * 40 + kk + 2 * qc;
                    uint32_t a0 = *(const uint32_t*)(ap);
                    uint32_t a1 = *(const uint32_t*)(ap + 8 * 40);
                    uint32_t a2 = *(const uint32_t*)(ap + 8);
                    uint32_t a3 = *(const uint32_t*)(ap + 8 * 40 + 8);
#pragma unroll
                    for (int f = 0; f < 4; f++) {
                        const bf16* bp = Kh + (ncS + f * 8 + qr) * 40 + kk + 2 * qc;
                        uint32_t b0 = *(const uint32_t*)(bp);
                        uint32_t b1 = *(const uint32_t*)(bp + 8);
                        mma_bf16(Sc[f], a0, a1, a2, a3, b0, b1);
                    }
                }
#pragma unroll
                for (int f = 0; f < 4; f++) {
                    int col = ncS + f * 8 + 2 * qc;
                    *(float2*)(Ss + (mrS + qr) * 66 + col)     = make_float2(Sc[f][0], Sc[f][1]);
                    *(float2*)(Ss + (mrS + qr + 8) * 66 + col) = make_float2(Sc[f][2], Sc[f][3]);
                }
            }
            __syncthreads();

            // softmax rows (8 per warp), write bf16 probabilities into Ps
#pragma unroll
            for (int rr = 0; rr < 8; rr++) {
                int row = w * 8 + rr;
                float2 v = *(const float2*)(Ss + row * 66 + 2 * lane);
                float mx = fmaxf(v.x, v.y);
#pragma unroll
                for (int off = 16; off; off >>= 1)
                    mx = fmaxf(mx, __shfl_xor_sync(0xffffffffu, mx, off));
                float e0 = __expf(v.x - mx), e1 = __expf(v.y - mx);
                float sv = e0 + e1;
#pragma unroll
                for (int off = 16; off; off >>= 1)
                    sv += __shfl_xor_sync(0xffffffffu, sv, off);
                float inv = 1.0f / sv;
                *(uint32_t*)(Ps + row * 72 + 2 * lane) = packbf(e0 * inv, e1 * inv);
            }
            __syncthreads();

            // O = P @ V^T  (64x32, K=64), warp tile 16x16; Vh is [d][hw]
            {
                float Oc[2][4];
#pragma unroll
                for (int f = 0; f < 2; f++)
#pragma unroll
                    for (int u = 0; u < 4; u++) Oc[f][u] = 0.0f;
#pragma unroll
                for (int ks = 0; ks < 4; ks++) {
                    int kk = ks * 16;
                    const bf16* ap = Ps + (mrS + qr) * 72 + kk + 2 * qc;
                    uint32_t a0 = *(const uint32_t*)(ap);
                    uint32_t a1 = *(const uint32_t*)(ap + 8 * 72);
                    uint32_t a2 = *(const uint32_t*)(ap + 8);
                    uint32_t a3 = *(const uint32_t*)(ap + 8 * 72 + 8);
#pragma unroll
                    for (int f = 0; f < 2; f++) {
                        const bf16* bp = Vh + (ncO + f * 8 + qr) * 72 + kk + 2 * qc;
                        uint32_t b0 = *(const uint32_t*)(bp);
                        uint32_t b1 = *(const uint32_t*)(bp + 8);
                        mma_bf16(Oc[f], a0, a1, a2, a3, b0, b1);
                    }
                }
#pragma unroll
                for (int f = 0; f < 2; f++) {
                    int col = h * 32 + ncO + f * 8 + 2 * qc;
                    *(uint32_t*)(Os + (mrS + qr) * 200 + col)     = packbf(Oc[f][0], Oc[f][1]);
                    *(uint32_t*)(Os + (mrS + qr + 8) * 200 + col) = packbf(Oc[f][2], Oc[f][3]);
                }
            }
            __syncthreads();
        }

        // ---------------- y = Os @ Wo^T + XP ----------------
#pragma unroll
        for (int a = 0; a < 2; a++)
#pragma unroll
            for (int f = 0; f < 6; f++)
#pragma unroll
                for (int u = 0; u < 4; u++) accs[a][f][u] = 0.0f;
        gemm_bf16(Os, Wproj, 2 * DIMC, Bs, accs, tid);
#pragma unroll
        for (int mf = 0; mf < 2; mf++)
#pragma unroll
            for (int f = 0; f < 6; f++) {
                int col = ncG + f * 8 + 2 * qc;
#pragma unroll
                for (int half = 0; half < 2; half++) {
                    int row = mrG + mf * 16 + qr + half * 8;
                    float2 xp = unpackbf(*(const uint32_t*)(XPs + row * 200 + col));
                    *(uint32_t*)(Ys + row * 200 + col) =
                        packbf(accs[mf][f][half * 2 + 0] + xp.x,
                               accs[mf][f][half * 2 + 1] + xp.y);
                }
            }
        __syncthreads();

        // ---------------- LayerNorm rows of Ys ----------------
#pragma unroll
        for (int rr = 0; rr < 8; rr++) {
            int row = w * 8 + rr;
            float2 vv[3];
            float s1 = 0.0f, s2 = 0.0f;
#pragma unroll
            for (int u = 0; u < 3; u++) {
                vv[u] = unpackbf(*(const uint32_t*)(Ys + row * 200 + 2 * lane + 64 * u));
                s1 += vv[u].x + vv[u].y;
                s2 += vv[u].x * vv[u].x + vv[u].y * vv[u].y;
            }
#pragma unroll
            for (int off = 16; off; off >>= 1) {
                s1 += __shfl_xor_sync(0xffffffffu, s1, off);
                s2 += __shfl_xor_sync(0xffffffffu, s2, off);
            }
            float mu = s1 * (1.0f / 192.0f);
            float var = s2 * (1.0f / 192.0f) - mu * mu;
            float rstd = rsqrtf(var + 1e-5f);
#pragma unroll
            for (int u = 0; u < 3; u++) {
                int c = 2 * lane + 64 * u;
                float y0 = (vv[u].x - mu) * rstd * __ldg(gamma + c)     + __ldg(beta + c);
                float y1 = (vv[u].y - mu) * rstd * __ldg(gamma + c + 1) + __ldg(beta + c + 1);
                *(uint32_t*)(Ys + row * 200 + c) = packbf(y0, y1);
            }
        }
        __syncthreads();

        // ---------------- Os = gelu(Ys @ W1^T + b1) ----------------
#pragma unroll
        for (int a = 0; a < 2; a++)
#pragma unroll
            for (int f = 0; f < 6; f++)
#pragma unroll
                for (int u = 0; u < 4; u++) accs[a][f][u] = 0.0f;
        gemm_bf16(Ys, W1, DIMC, Bs, accs, tid);
#pragma unroll
        for (int mf = 0; mf < 2; mf++)
#pragma unroll
            for (int f = 0; f < 6; f++) {
                int col = ncG + f * 8 + 2 * qc;
                float b0v = __ldg(b1 + col), b1v = __ldg(b1 + col + 1);
#pragma unroll
                for (int half = 0; half < 2; half++) {
                    int row = mrG + mf * 16 + qr + half * 8;
                    float h0 = accs[mf][f][half * 2 + 0] + b0v;
                    float h1 = accs[mf][f][half * 2 + 1] + b1v;
                    float g0 = 0.5f * h0 * (1.0f + erff(h0 * 0.70710678118654752f));
                    float g1 = 0.5f * h1 * (1.0f + erff(h1 * 0.70710678118654752f));
                    *(uint32_t*)(Os + row * 200 + col) = packbf(g0, g1);
                }
            }
        __syncthreads();

        // ---------------- accF += Os @ W2^T ----------------
        gemm_bf16(Os, W2, DIMC, Bs, accF, tid);
        // ends with __syncthreads -> union region reusable next j
    }

    // ---------------- write out: [x | x + acc/T + b2] ----------------
#pragma unroll
    for (int mf = 0; mf < 2; mf++)
#pragma unroll
        for (int f = 0; f < 6; f++) {
            int col = ncG + f * 8 + 2 * qc;
            float b20 = __ldg(b2 + col), b21 = __ldg(b2 + col + 1);
#pragma unroll
            for (int half = 0; half < 2; half++) {
                int row = mrG + mf * 16 + qr + half * 8;
                int n = i * 64 + row;
                size_t base = (size_t)bb * NTOK + n;
                float2 xv = *(const float2*)(x + base * DIMC + col);
                *(float2*)(out + base * (2 * DIMC) + col) = xv;
                float2 ov;
                ov.x = xv.x + accF[mf][f][half * 2 + 0] * (1.0f / 6.0f) + b20;
                ov.y = xv.y + accF[mf][f][half * 2 + 1] * (1.0f / 6.0f) + b21;
                *(float2*)(out + base * (2 * DIMC) + DIMC + col) = ov;
            }
        }
}

// ---------------------------------------------------------------------------
extern "C" void kernel_launch(void* const* d_in, const int* in_sizes, int n_in,
                              void* d_out, int out_size) {
    (void)in_sizes; (void)n_in; (void)out_size;
    const float* x     = (const float*)d_in[0];
    const float* Wqkv  = (const float*)d_in[1];
    const float* Wproj = (const float*)d_in[2];
    const float* bproj = (const float*)d_in[3];
    const float* gamma = (const float*)d_in[4];
    const float* beta  = (const float*)d_in[5];
    const float* W1    = (const float*)d_in[6];
    const float* b1    = (const float*)d_in[7];
    const float* W2    = (const float*)d_in[8];
    const float* b2    = (const float*)d_in[9];
    float* out = (float*)d_out;

    pos_kernel<<<48, 256>>>();

    const int qkv_smem = 25600 + 27648;  // 53248 B
    cudaFuncSetAttribute(qkv_kernel, cudaFuncAttributeMaxDynamicSharedMemorySize, qkv_smem);
    qkv_kernel<<<dim3(768, 3), 256, qkv_smem>>>(x, Wqkv);

    const int main_smem = 108544;
    cudaFuncSetAttribute(main_kernel, cudaFuncAttributeMaxDynamicSharedMemorySize, main_smem);
    main_kernel<<<dim3(TT, NB), 256, main_smem>>>(x, Wproj, bproj, gamma, beta,
                                                  W1, b1, W2, b2, out);
}

// round 5
// speedup vs baseline: 4.6966x; 1.1667x over previous
#include <cuda_runtime.h>
#include <cuda_bf16.h>
#include <math.h>
#include <stdint.h>

// ---------------------------------------------------------------------------
// WindowAttention3D fused kernel, bf16 mma + ldmatrix + cp.async version.
// B=128, T=6, H=W=8 (HW=64), N=384, DIM=192, NH=6, HD=32.
// ---------------------------------------------------------------------------

#define NB    128
#define TT    6
#define HWN   64
#define NTOK  384
#define DIMC  192
#define NHEAD 6
#define HDIM  32

typedef __nv_bfloat16 bf16;

// scratch (device globals: allocation-free). Q/K: [b][h][t][hw][d]; Vt: [b][h][t][d][hw]
__device__ bf16 g_Q [NB * NHEAD * TT * HWN * HDIM];
__device__ bf16 g_K [NB * NHEAD * TT * HWN * HDIM];
__device__ bf16 g_Vt[NB * NHEAD * TT * HWN * HDIM];
__device__ float g_pos[HWN * DIMC];
// bf16 weights, [n][k] row-major, k-stride 192
__device__ bf16 g_Wqkv[3 * DIMC * DIMC];
__device__ bf16 g_Wo[DIMC * DIMC];
__device__ bf16 g_Wx[DIMC * DIMC];
__device__ bf16 g_W1b[DIMC * DIMC];
__device__ bf16 g_W2b[DIMC * DIMC];

// ---------------------------------------------------------------------------
__device__ __forceinline__ void mma_bf16(float* c, uint32_t a0, uint32_t a1,
                                         uint32_t a2, uint32_t a3,
                                         uint32_t b0, uint32_t b1) {
    asm volatile(
        "mma.sync.aligned.m16n8k16.row.col.f32.bf16.bf16.f32 "
        "{%0,%1,%2,%3}, {%4,%5,%6,%7}, {%8,%9}, {%0,%1,%2,%3};\n"
        : "+f"(c[0]), "+f"(c[1]), "+f"(c[2]), "+f"(c[3])
        : "r"(a0), "r"(a1), "r"(a2), "r"(a3), "r"(b0), "r"(b1));
}

__device__ __forceinline__ void ldsm4(uint32_t* r, uint32_t addr) {
    asm volatile("ldmatrix.sync.aligned.m8n8.x4.shared.b16 {%0,%1,%2,%3}, [%4];"
                 : "=r"(r[0]), "=r"(r[1]), "=r"(r[2]), "=r"(r[3]) : "r"(addr));
}

__device__ __forceinline__ void cp16(uint32_t saddr, const void* gaddr) {
    asm volatile("cp.async.cg.shared.global [%0], [%1], 16;" :: "r"(saddr), "l"(gaddr));
}
__device__ __forceinline__ void cp_commit() { asm volatile("cp.async.commit_group;"); }
template <int N> __device__ __forceinline__ void cp_wait() {
    asm volatile("cp.async.wait_group %0;" :: "n"(N));
}

__device__ __forceinline__ uint32_t s2u(const void* p) {
    return (uint32_t)__cvta_generic_to_shared(p);
}

__device__ __forceinline__ uint32_t packbf(float lo, float hi) {
    uint32_t r;
    asm("cvt.rn.bf16x2.f32 %0, %1, %2;" : "=r"(r) : "f"(hi), "f"(lo));
    return r;
}
__device__ __forceinline__ float2 unpackbf(uint32_t p) {
    __nv_bfloat162 b = *reinterpret_cast<__nv_bfloat162*>(&p);
    return make_float2(__bfloat162float(b.x), __bfloat162float(b.y));
}

// ---------------------------------------------------------------------------
// Kernel 0: weight conversion fp32 -> bf16
// ---------------------------------------------------------------------------
__global__ void prep_kernel(const float* __restrict__ Wqkv, const float* __restrict__ Wproj,
                            const float* __restrict__ W1, const float* __restrict__ W2) {
    int idx = blockIdx.x * 256 + threadIdx.x;
    if (idx < 3 * DIMC * DIMC) g_Wqkv[idx] = __float2bfloat16(Wqkv[idx]);
    if (idx < DIMC * DIMC) {
        int n = idx / DIMC, k = idx % DIMC;
        g_Wo[idx]  = __float2bfloat16(Wproj[n * 384 + k]);
        g_Wx[idx]  = __float2bfloat16(Wproj[n * 384 + 192 + k]);
        g_W1b[idx] = __float2bfloat16(W1[idx]);
        g_W2b[idx] = __float2bfloat16(W2[idx]);
    }
}

// ---------------------------------------------------------------------------
// Kernel 1: sine positional encoding (64 x 192)
// ---------------------------------------------------------------------------
__global__ void pos_kernel() {
    int idx = blockIdx.x * blockDim.x + threadIdx.x;
    if (idx >= HWN * DIMC) return;
    int hw = idx / DIMC, c = idx % DIMC;
    int row = hw >> 3, col = hw & 7;
    const float two_pi = 6.2831853071795864769f;
    const float inv_denom = two_pi / (8.0f + 1e-6f);
    int m;
    float embed;
    if (c < 96) { m = c >> 1;        embed = (float)(row + 1) * inv_denom; }
    else        { m = (c - 96) >> 1; embed = (float)(col + 1) * inv_denom; }
    float freq = powf(10000.0f, (float)m * (1.0f / 48.0f));
    float v = embed / freq;
    g_pos[idx] = (c & 1) ? cosf(v) : sinf(v);
}

// ---------------------------------------------------------------------------
// bf16 warp-mma GEMM: C[2][6][4] += A(64x192 bf16, stride 200) @ Wbf^T
// Wbf bf16 global [192][192]. Buf = 2 ping-pong stage buffers, each 192x40 bf16
// (15360 B), cp.async double-buffered in 32-k chunks. ldmatrix fragments.
// 8 warps: warp tile rows (w&1)*32..+31, cols (w>>1)*48..+47.
// ---------------------------------------------------------------------------
__device__ __forceinline__ void gemm_bf16(const bf16* __restrict__ As,
                                          const bf16* __restrict__ Wbf,
                                          bf16* __restrict__ Buf,
                                          float C[2][6][4], int tid) {
    int lane = tid & 31, w = tid >> 5;
    int mr = (w & 1) * 32, nc = (w >> 1) * 48;
    uint32_t bufu = s2u(Buf);
    uint32_t asu = s2u(As);
    uint32_t a_off0 = asu + ((mr + (lane & 15)) * 200 + ((lane >> 4) << 3)) * 2;
    uint32_t a_off1 = a_off0 + 16 * 200 * 2;
    int bn = (lane & 7) + ((lane >> 4) << 3);   // + nc + p*16 -> B row
    int bk = ((lane >> 3) & 1) << 3;            // k half within 16

    // staging map: idx = tid + i*256 in [0,768): n = idx>>2, kq = (idx&3)*8
    int sn = tid >> 2, skq = (tid & 3) * 8;

    // prefetch chunk 0 into buffer 0
#pragma unroll
    for (int i2 = 0; i2 < 3; i2++) {
        int n = sn + i2 * 64;
        cp16(bufu + n * 80 + skq * 2, Wbf + n * DIMC + skq);
    }
    cp_commit();

#pragma unroll 1
    for (int c = 0; c < 6; c++) {
        if (c < 5) {
            const bf16* Wsrc = Wbf + (c + 1) * 32;
            uint32_t dstb = bufu + ((c + 1) & 1) * 15360;
#pragma unroll
            for (int i2 = 0; i2 < 3; i2++) {
                int n = sn + i2 * 64;
                cp16(dstb + n * 80 + skq * 2, Wsrc + n * DIMC + skq);
            }
            cp_commit();
            cp_wait<1>();
        } else {
            cp_wait<0>();
        }
        __syncthreads();
        uint32_t bb = bufu + (c & 1) * 15360;
#pragma unroll
        for (int ks = 0; ks < 2; ks++) {
            int kg = c * 32 + ks * 16;
            uint32_t a0[4], a1[4];
            ldsm4(a0, a_off0 + kg * 2);
            ldsm4(a1, a_off1 + kg * 2);
#pragma unroll
            for (int p = 0; p < 3; p++) {
                uint32_t b[4];
                ldsm4(b, bb + ((nc + p * 16 + bn) * 40 + ks * 16 + bk) * 2);
                mma_bf16(C[0][2 * p],     a0[0], a0[1], a0[2], a0[3], b[0], b[1]);
                mma_bf16(C[1][2 * p],     a1[0], a1[1], a1[2], a1[3], b[0], b[1]);
                mma_bf16(C[0][2 * p + 1], a0[0], a0[1], a0[2], a0[3], b[2], b[3]);
                mma_bf16(C[1][2 * p + 1], a1[0], a1[1], a1[2], a1[3], b[2], b[3]);
            }
        }
        __syncthreads();
    }
}

// ---------------------------------------------------------------------------
// Kernel 2: qkv = (x + pos) @ Wqkv^T, scatter into g_Q/g_K/g_Vt.
// grid (768, 3). smem: As bf16 64x200 (25600B) + stage buffers (30720B).
// ---------------------------------------------------------------------------
__global__ __launch_bounds__(256, 2) void qkv_kernel(const float* __restrict__ x) {
    extern __shared__ char smc[];
    bf16* As  = (bf16*)smc;              // 64*200
    bf16* Buf = (bf16*)(smc + 25600);    // 2 x 192*40

    int tid = threadIdx.x;
    int lane = tid & 31, w = tid >> 5;
    int qr = lane >> 2, qc = lane & 3;
    int r0 = blockIdx.x * 64;
    int s = blockIdx.y;

    // stage A = bf16(x + pos)
#pragma unroll
    for (int q = tid; q < 1536; q += 256) {
        int r = q / 24, c8 = (q % 24) * 8;
        float4 x0 = *(const float4*)(x + (size_t)(r0 + r) * DIMC + c8);
        float4 x1 = *(const float4*)(x + (size_t)(r0 + r) * DIMC + c8 + 4);
        float4 p0 = *(const float4*)(g_pos + r * DIMC + c8);
        float4 p1 = *(const float4*)(g_pos + r * DIMC + c8 + 4);
        uint4 o;
        o.x = packbf(x0.x + p0.x, x0.y + p0.y);
        o.y = packbf(x0.z + p0.z, x0.w + p0.w);
        o.z = packbf(x1.x + p1.x, x1.y + p1.y);
        o.w = packbf(x1.z + p1.z, x1.w + p1.w);
        *(uint4*)(As + r * 200 + c8) = o;
    }
    __syncthreads();

    float C[2][6][4];
#pragma unroll
    for (int a = 0; a < 2; a++)
#pragma unroll
        for (int f = 0; f < 6; f++)
#pragma unroll
            for (int u = 0; u < 4; u++) C[a][f][u] = 0.0f;

    gemm_bf16(As, g_Wqkv + (size_t)s * DIMC * DIMC, Buf, C, tid);

    const float SCALE = 0.17677669529663688f;  // 32^-0.5
    int mr = (w & 1) * 32, nc = (w >> 1) * 48;

    if (s < 2) {
        bf16* GD = (s == 0) ? g_Q : g_K;
        float scl = (s == 0) ? SCALE : 1.0f;
#pragma unroll
        for (int mf = 0; mf < 2; mf++)
#pragma unroll
            for (int f = 0; f < 6; f++) {
                int cg = nc + f * 8 + 2 * qc;
                int h = cg >> 5, d = cg & 31;
#pragma unroll
                for (int half = 0; half < 2; half++) {
                    int gr = r0 + mr + mf * 16 + qr + half * 8;
                    int bidx = gr / NTOK, n = gr % NTOK;
                    int t = n >> 6, hw = n & 63;
                    int dst = ((bidx * NHEAD + h) * TT + t) * 2048 + hw * 32 + d;
                    *(uint32_t*)(GD + dst) =
                        packbf(C[mf][f][half * 2 + 0] * scl, C[mf][f][half * 2 + 1] * scl);
                }
            }
    } else {
        // V transposed: [b][h][t][d][hw]
#pragma unroll
        for (int mf = 0; mf < 2; mf++)
#pragma unroll
            for (int f = 0; f < 6; f++) {
                int cg = nc + f * 8 + 2 * qc;
                int h = cg >> 5, d = cg & 31;
#pragma unroll
                for (int half = 0; half < 2; half++) {
                    int gr = r0 + mr + mf * 16 + qr + half * 8;
                    int bidx = gr / NTOK, n = gr % NTOK;
                    int t = n >> 6, hw = n & 63;
                    int base = ((bidx * NHEAD + h) * TT + t) * 2048;
                    g_Vt[base + d * 64 + hw]       = __float2bfloat16(C[mf][f][half * 2 + 0]);
                    g_Vt[base + (d + 1) * 64 + hw] = __float2bfloat16(C[mf][f][half * 2 + 1]);
                }
            }
    }
}

// ---------------------------------------------------------------------------
// Kernel 3: per-(i, b) fused attention + proj + LN + MLP + j-accumulate + out.
// grid (6, 128), 256 threads, 108544 B dynamic smem -> 2 CTAs/SM.
// ---------------------------------------------------------------------------
__global__ __launch_bounds__(256, 2) void main_kernel(
    const float* __restrict__ x,
    const float* __restrict__ bproj, const float* __restrict__ gamma,
    const float* __restrict__ beta, const float* __restrict__ b1,
    const float* __restrict__ b2, float* __restrict__ out) {
    extern __shared__ char smc[];
    bf16* XPs = (bf16*)smc;                 // 64*200 = 25600 B
    bf16* Os  = (bf16*)(smc + 25600);       // 64*200
    bf16* Ys  = (bf16*)(smc + 51200);       // 64*200
    // union region @76800 (31744 B):
    bf16*  Buf = (bf16*)(smc + 76800);      // gemm stage: 2 x 15360 B
    bf16*  Qh = (bf16*)(smc + 76800);       // 64*40 = 5120 B
    bf16*  Kh = (bf16*)(smc + 81920);       // 64*40 = 5120 B
    bf16*  Vh = (bf16*)(smc + 87040);       // 32*72 = 4608 B
    float* Ss = (float*)(smc + 91648);      // 64*66*4 = 16896 B -> end 108544
    bf16*  Ps = (bf16*)(smc + 76800);       // 64*72 = 9216 B (aliases Qh/Kh)

    int tid = threadIdx.x;
    int lane = tid & 31, w = tid >> 5;
    int qr = lane >> 2, qc = lane & 3;
    int i = blockIdx.x, bb = blockIdx.y;

    int mrG = (w & 1) * 32, ncG = (w >> 1) * 48;   // gemm warp tile
    int mrS = (w & 3) * 16, ncS = (w >> 2) * 32;   // S warp tile
    int ncO = (w >> 2) * 16;                       // P@V warp tile

    int bn = (lane & 7) + ((lane >> 4) << 3);
    int bk = ((lane >> 3) & 1) << 3;

    // ---- XP = x_flat[R] @ Wx^T + bproj (j-invariant; torch .view reinterpret) ----
    {
        size_t Rbase = (size_t)i * 8192 + (size_t)bb * 64;
#pragma unroll
        for (int q = tid; q < 1536; q += 256) {
            int r = q / 24, c8 = (q % 24) * 8;
            float4 x0 = *(const float4*)(x + (Rbase + r) * DIMC + c8);
            float4 x1 = *(const float4*)(x + (Rbase + r) * DIMC + c8 + 4);
            uint4 o;
            o.x = packbf(x0.x, x0.y);
            o.y = packbf(x0.z, x0.w);
            o.z = packbf(x1.x, x1.y);
            o.w = packbf(x1.z, x1.w);
            *(uint4*)(Ys + r * 200 + c8) = o;
        }
    }
    __syncthreads();

    float accs[2][6][4];
#pragma unroll
    for (int a = 0; a < 2; a++)
#pragma unroll
        for (int f = 0; f < 6; f++)
#pragma unroll
            for (int u = 0; u < 4; u++) accs[a][f][u] = 0.0f;
    gemm_bf16(Ys, g_Wx, Buf, accs, tid);
#pragma unroll
    for (int mf = 0; mf < 2; mf++)
#pragma unroll
        for (int f = 0; f < 6; f++) {
            int col = ncG + f * 8 + 2 * qc;
            float b0v = __ldg(bproj + col), b1v = __ldg(bproj + col + 1);
#pragma unroll
            for (int half = 0; half < 2; half++) {
                int row = mrG + mf * 16 + qr + half * 8;
                *(uint32_t*)(XPs + row * 200 + col) =
                    packbf(accs[mf][f][half * 2 + 0] + b0v, accs[mf][f][half * 2 + 1] + b1v);
            }
        }
    __syncthreads();

    float accF[2][6][4];
#pragma unroll
    for (int a = 0; a < 2; a++)
#pragma unroll
        for (int f = 0; f < 6; f++)
#pragma unroll
            for (int u = 0; u < 4; u++) accF[a][f][u] = 0.0f;

#pragma unroll 1
    for (int j = 0; j < TT; j++) {
        // ---------------- attention: Os[r][h*32+d] ----------------
#pragma unroll 1
        for (int h = 0; h < NHEAD; h++) {
            const bf16* Qg = g_Q  + ((size_t)((bb * NHEAD + h) * TT + i) << 11);
            const bf16* Kg = g_K  + ((size_t)((bb * NHEAD + h) * TT + j) << 11);
            const bf16* Vg = g_Vt + ((size_t)((bb * NHEAD + h) * TT + j) << 11);
            {
                int r = tid >> 2, c8 = (tid & 3) * 8;
                *(uint4*)(Qh + r * 40 + c8) = *(const uint4*)(Qg + r * 32 + c8);
                *(uint4*)(Kh + r * 40 + c8) = *(const uint4*)(Kg + r * 32 + c8);
                int rv = tid >> 3, cv = (tid & 7) * 8;
                *(uint4*)(Vh + rv * 72 + cv) = *(const uint4*)(Vg + rv * 64 + cv);
            }
            __syncthreads();

            // S = Q @ K^T  (64x64, K=32), warp tile 16x32, ldmatrix fragments
            {
                float Sc[4][4];
#pragma unroll
                for (int f = 0; f < 4; f++)
#pragma unroll
                    for (int u = 0; u < 4; u++) Sc[f][u] = 0.0f;
                uint32_t qbase = s2u(Qh) + ((mrS + (lane & 15)) * 40 + ((lane >> 4) << 3)) * 2;
                uint32_t kbase = s2u(Kh);
#pragma unroll
                for (int ks = 0; ks < 2; ks++) {
                    uint32_t a[4];
                    ldsm4(a, qbase + ks * 16 * 2);
#pragma unroll
                    for (int p = 0; p < 2; p++) {
                        uint32_t b[4];
                        ldsm4(b, kbase + ((ncS + p * 16 + bn) * 40 + ks * 16 + bk) * 2);
                        mma_bf16(Sc[2 * p],     a[0], a[1], a[2], a[3], b[0], b[1]);
                        mma_bf16(Sc[2 * p + 1], a[0], a[1], a[2], a[3], b[2], b[3]);
                    }
                }
#pragma unroll
                for (int f = 0; f < 4; f++) {
                    int col = ncS + f * 8 + 2 * qc;
                    *(float2*)(Ss + (mrS + qr) * 66 + col)     = make_float2(Sc[f][0], Sc[f][1]);
                    *(float2*)(Ss + (mrS + qr + 8) * 66 + col) = make_float2(Sc[f][2], Sc[f][3]);
                }
            }
            __syncthreads();

            // softmax rows (8 per warp), write bf16 probabilities into Ps
#pragma unroll
            for (int rr = 0; rr < 8; rr++) {
                int row = w * 8 + rr;
                float2 v = *(const float2*)(Ss + row * 66 + 2 * lane);
                float mx = fmaxf(v.x, v.y);
#pragma unroll
                for (int off = 16; off; off >>= 1)
                    mx = fmaxf(mx, __shfl_xor_sync(0xffffffffu, mx, off));
                float e0 = __expf(v.x - mx), e1 = __expf(v.y - mx);
                float sv = e0 + e1;
#pragma unroll
                for (int off = 16; off; off >>= 1)
                    sv += __shfl_xor_sync(0xffffffffu, sv, off);
                float inv = 1.0f / sv;
                *(uint32_t*)(Ps + row * 72 + 2 * lane) = packbf(e0 * inv, e1 * inv);
            }
            __syncthreads();

            // O = P @ V^T  (64x32, K=64), warp tile 16x16; Vh is [d][hw]
            {
                float Oc[2][4];
#pragma unroll
                for (int f = 0; f < 2; f++)
#pragma unroll
                    for (int u = 0; u < 4; u++) Oc[f][u] = 0.0f;
                uint32_t pbase = s2u(Ps) + ((mrS + (lane & 15)) * 72 + ((lane >> 4) << 3)) * 2;
                uint32_t vbase = s2u(Vh);
#pragma unroll
                for (int ks = 0; ks < 4; ks++) {
                    uint32_t a[4], b[4];
                    ldsm4(a, pbase + ks * 16 * 2);
                    ldsm4(b, vbase + ((ncO + bn) * 72 + ks * 16 + bk) * 2);
                    mma_bf16(Oc[0], a[0], a[1], a[2], a[3], b[0], b[1]);
                    mma_bf16(Oc[1], a[0], a[1], a[2], a[3], b[2], b[3]);
                }
#pragma unroll
                for (int f = 0; f < 2; f++) {
                    int col = h * 32 + ncO + f * 8 + 2 * qc;
                    *(uint32_t*)(Os + (mrS + qr) * 200 + col)     = packbf(Oc[f][0], Oc[f][1]);
                    *(uint32_t*)(Os + (mrS + qr + 8) * 200 + col) = packbf(Oc[f][2], Oc[f][3]);
                }
            }
            __syncthreads();
        }

        // ---------------- y = Os @ Wo^T + XP ----------------
#pragma unroll
        for (int a = 0; a < 2; a++)
#pragma unroll
            for (int f = 0; f < 6; f++)
#pragma unroll
                for (int u = 0; u < 4; u++) accs[a][f][u] = 0.0f;
        gemm_bf16(Os, g_Wo, Buf, accs, tid);
#pragma unroll
        for (int mf = 0; mf < 2; mf++)
#pragma unroll
            for (int f = 0; f < 6; f++) {
                int col = ncG + f * 8 + 2 * qc;
#pragma unroll
                for (int half = 0; half < 2; half++) {
                    int row = mrG + mf * 16 + qr + half * 8;
                    float2 xp = unpackbf(*(const uint32_t*)(XPs + row * 200 + col));
                    *(uint32_t*)(Ys + row * 200 + col) =
                        packbf(accs[mf][f][half * 2 + 0] + xp.x,
                               accs[mf][f][half * 2 + 1] + xp.y);
                }
            }
        __syncthreads();

        // ---------------- LayerNorm rows of Ys ----------------
#pragma unroll
        for (int rr = 0; rr < 8; rr++) {
            int row = w * 8 + rr;
            float2 vv[3];
            float s1 = 0.0f, s2 = 0.0f;
#pragma unroll
            for (int u = 0; u < 3; u++) {
                vv[u] = unpackbf(*(const uint32_t*)(Ys + row * 200 + 2 * lane + 64 * u));
                s1 += vv[u].x + vv[u].y;
                s2 += vv[u].x * vv[u].x + vv[u].y * vv[u].y;
            }
#pragma unroll
            for (int off = 16; off; off >>= 1) {
                s1 += __shfl_xor_sync(0xffffffffu, s1, off);
                s2 += __shfl_xor_sync(0xffffffffu, s2, off);
            }
            float mu = s1 * (1.0f / 192.0f);
            float var = s2 * (1.0f / 192.0f) - mu * mu;
            float rstd = rsqrtf(var + 1e-5f);
#pragma unroll
            for (int u = 0; u < 3; u++) {
                int c = 2 * lane + 64 * u;
                float y0 = (vv[u].x - mu) * rstd * __ldg(gamma + c)     + __ldg(beta + c);
                float y1 = (vv[u].y - mu) * rstd * __ldg(gamma + c + 1) + __ldg(beta + c + 1);
                *(uint32_t*)(Ys + row * 200 + c) = packbf(y0, y1);
            }
        }
        __syncthreads();

        // ---------------- Os = gelu(Ys @ W1^T + b1) ----------------
#pragma unroll
        for (int a = 0; a < 2; a++)
#pragma unroll
            for (int f = 0; f < 6; f++)
#pragma unroll
                for (int u = 0; u < 4; u++) accs[a][f][u] = 0.0f;
        gemm_bf16(Ys, g_W1b, Buf, accs, tid);
#pragma unroll
        for (int mf = 0; mf < 2; mf++)
#pragma unroll
            for (int f = 0; f < 6; f++) {
                int col = ncG + f * 8 + 2 * qc;
                float b0v = __ldg(b1 + col), b1v = __ldg(b1 + col + 1);
#pragma unroll
                for (int half = 0; half < 2; half++) {
                    int row = mrG + mf * 16 + qr + half * 8;
                    float h0 = accs[mf][f][half * 2 + 0] + b0v;
                    float h1 = accs[mf][f][half * 2 + 1] + b1v;
                    float g0 = 0.5f * h0 * (1.0f + erff(h0 * 0.70710678118654752f));
                    float g1 = 0.5f * h1 * (1.0f + erff(h1 * 0.70710678118654752f));
                    *(uint32_t*)(Os + row * 200 + col) = packbf(g0, g1);
                }
            }
        __syncthreads();

        // ---------------- accF += Os @ W2^T ----------------
        gemm_bf16(Os, g_W2b, Buf, accF, tid);
        // ends with __syncthreads -> union region reusable next j
    }

    // ---------------- write out: [x | x + acc/T + b2] ----------------
#pragma unroll
    for (int mf = 0; mf < 2; mf++)
#pragma unroll
        for (int f = 0; f < 6; f++) {
            int col = ncG + f * 8 + 2 * qc;
            float b20 = __ldg(b2 + col), b21 = __ldg(b2 + col + 1);
#pragma unroll
            for (int half = 0; half < 2; half++) {
                int row = mrG + mf * 16 + qr + half * 8;
                int n = i * 64 + row;
                size_t base = (size_t)bb * NTOK + n;
                float2 xv = *(const float2*)(x + base * DIMC + col);
                *(float2*)(out + base * (2 * DIMC) + col) = xv;
                float2 ov;
                ov.x = xv.x + accF[mf][f][half * 2 + 0] * (1.0f / 6.0f) + b20;
                ov.y = xv.y + accF[mf][f][half * 2 + 1] * (1.0f / 6.0f) + b21;
                *(float2*)(out + base * (2 * DIMC) + DIMC + col) = ov;
            }
        }
}

// ---------------------------------------------------------------------------
extern "C" void kernel_launch(void* const* d_in, const int* in_sizes, int n_in,
                              void* d_out, int out_size) {
    (void)in_sizes; (void)n_in; (void)out_size;
    const float* x     = (const float*)d_in[0];
    const float* Wqkv  = (const float*)d_in[1];
    const float* Wproj = (const float*)d_in[2];
    const float* bproj = (const float*)d_in[3];
    const float* gamma = (const float*)d_in[4];
    const float* beta  = (const float*)d_in[5];
    const float* W1    = (const float*)d_in[6];
    const float* b1    = (const float*)d_in[7];
    const float* W2    = (const float*)d_in[8];
    const float* b2    = (const float*)d_in[9];
    float* out = (float*)d_out;

    prep_kernel<<<432, 256>>>(Wqkv, Wproj, W1, W2);
    pos_kernel<<<48, 256>>>();

    const int qkv_smem = 25600 + 30720;  // 56320 B
    cudaFuncSetAttribute(qkv_kernel, cudaFuncAttributeMaxDynamicSharedMemorySize, qkv_smem);
    qkv_kernel<<<dim3(768, 3), 256, qkv_smem>>>(x);

    const int main_smem = 108544;
    cudaFuncSetAttribute(main_kernel, cudaFuncAttributeMaxDynamicSharedMemorySize, main_smem);
    main_kernel<<<dim3(TT, NB), 256, main_smem>>>(x, bproj, gamma, beta, b1, b2, out);
}

// round 6
// speedup vs baseline: 6.1468x; 1.3088x over previous
#include <cuda_runtime.h>
#include <cuda_bf16.h>
#include <math.h>
#include <stdint.h>

// ---------------------------------------------------------------------------
// WindowAttention3D fused kernel, bf16 mma + ldmatrix + cp.async,
// register softmax + resident Q + double-buffered K/V.
// B=128, T=6, H=W=8 (HW=64), N=384, DIM=192, NH=6, HD=32.
// ---------------------------------------------------------------------------

#define NB    128
#define TT    6
#define HWN   64
#define NTOK  384
#define DIMC  192
#define NHEAD 6
#define HDIM  32

typedef __nv_bfloat16 bf16;

// scratch (device globals: allocation-free). Q/K: [b][h][t][hw][d]; Vt: [b][h][t][d][hw]
__device__ bf16 g_Q [NB * NHEAD * TT * HWN * HDIM];
__device__ bf16 g_K [NB * NHEAD * TT * HWN * HDIM];
__device__ bf16 g_Vt[NB * NHEAD * TT * HWN * HDIM];
__device__ bf16 g_XP[TT * NB * HWN * DIMC];   // XP = x@Wx^T + bproj, per (i,b)
__device__ float g_pos[HWN * DIMC];
// bf16 weights, [n][k] row-major, k-stride 192
__device__ bf16 g_Wqkv[3 * DIMC * DIMC];
__device__ bf16 g_Wo[DIMC * DIMC];
__device__ bf16 g_Wx[DIMC * DIMC];
__device__ bf16 g_W1b[DIMC * DIMC];
__device__ bf16 g_W2b[DIMC * DIMC];

// ---------------------------------------------------------------------------
__device__ __forceinline__ void mma_bf16(float* c, uint32_t a0, uint32_t a1,
                                         uint32_t a2, uint32_t a3,
                                         uint32_t b0, uint32_t b1) {
    asm volatile(
        "mma.sync.aligned.m16n8k16.row.col.f32.bf16.bf16.f32 "
        "{%0,%1,%2,%3}, {%4,%5,%6,%7}, {%8,%9}, {%0,%1,%2,%3};\n"
        : "+f"(c[0]), "+f"(c[1]), "+f"(c[2]), "+f"(c[3])
        : "r"(a0), "r"(a1), "r"(a2), "r"(a3), "r"(b0), "r"(b1));
}

__device__ __forceinline__ void ldsm4(uint32_t* r, uint32_t addr) {
    asm volatile("ldmatrix.sync.aligned.m8n8.x4.shared.b16 {%0,%1,%2,%3}, [%4];"
                 : "=r"(r[0]), "=r"(r[1]), "=r"(r[2]), "=r"(r[3]) : "r"(addr));
}

__device__ __forceinline__ void cp16(uint32_t saddr, const void* gaddr) {
    asm volatile("cp.async.cg.shared.global [%0], [%1], 16;" :: "r"(saddr), "l"(gaddr));
}
__device__ __forceinline__ void cp_commit() { asm volatile("cp.async.commit_group;"); }
template <int N> __device__ __forceinline__ void cp_wait() {
    asm volatile("cp.async.wait_group %0;" :: "n"(N));
}

__device__ __forceinline__ uint32_t s2u(const void* p) {
    return (uint32_t)__cvta_generic_to_shared(p);
}

__device__ __forceinline__ uint32_t packbf(float lo, float hi) {
    uint32_t r;
    asm("cvt.rn.bf16x2.f32 %0, %1, %2;" : "=r"(r) : "f"(hi), "f"(lo));
    return r;
}
__device__ __forceinline__ float2 unpackbf(uint32_t p) {
    __nv_bfloat162 b = *reinterpret_cast<__nv_bfloat162*>(&p);
    return make_float2(__bfloat162float(b.x), __bfloat162float(b.y));
}

// ---------------------------------------------------------------------------
// Kernel 0: weight conversion fp32 -> bf16
// ---------------------------------------------------------------------------
__global__ void prep_kernel(const float* __restrict__ Wqkv, const float* __restrict__ Wproj,
                            const float* __restrict__ W1, const float* __restrict__ W2) {
    int idx = blockIdx.x * 256 + threadIdx.x;
    if (idx < 3 * DIMC * DIMC) g_Wqkv[idx] = __float2bfloat16(Wqkv[idx]);
    if (idx < DIMC * DIMC) {
        int n = idx / DIMC, k = idx % DIMC;
        g_Wo[idx]  = __float2bfloat16(Wproj[n * 384 + k]);
        g_Wx[idx]  = __float2bfloat16(Wproj[n * 384 + 192 + k]);
        g_W1b[idx] = __float2bfloat16(W1[idx]);
        g_W2b[idx] = __float2bfloat16(W2[idx]);
    }
}

// ---------------------------------------------------------------------------
// Kernel 1: sine positional encoding (64 x 192)
// ---------------------------------------------------------------------------
__global__ void pos_kernel() {
    int idx = blockIdx.x * blockDim.x + threadIdx.x;
    if (idx >= HWN * DIMC) return;
    int hw = idx / DIMC, c = idx % DIMC;
    int row = hw >> 3, col = hw & 7;
    const float two_pi = 6.2831853071795864769f;
    const float inv_denom = two_pi / (8.0f + 1e-6f);
    int m;
    float embed;
    if (c < 96) { m = c >> 1;        embed = (float)(row + 1) * inv_denom; }
    else        { m = (c - 96) >> 1; embed = (float)(col + 1) * inv_denom; }
    float freq = powf(10000.0f, (float)m * (1.0f / 48.0f));
    float v = embed / freq;
    g_pos[idx] = (c & 1) ? cosf(v) : sinf(v);
}

// ---------------------------------------------------------------------------
// bf16 warp-mma GEMM: C[2][6][4] += A(64x192 bf16, stride 200) @ Wbf^T
// Wbf bf16 global [192][192]. Buf = 2 ping-pong stage buffers, each 192x40 bf16
// (15360 B), cp.async double-buffered in 32-k chunks. ldmatrix fragments.
// 8 warps: warp tile rows (w&1)*32..+31, cols (w>>1)*48..+47.
// ---------------------------------------------------------------------------
__device__ __forceinline__ void gemm_bf16(const bf16* __restrict__ As,
                                          const bf16* __restrict__ Wbf,
                                          bf16* __restrict__ Buf,
                                          float C[2][6][4], int tid) {
    int lane = tid & 31, w = tid >> 5;
    int mr = (w & 1) * 32, nc = (w >> 1) * 48;
    uint32_t bufu = s2u(Buf);
    uint32_t asu = s2u(As);
    uint32_t a_off0 = asu + ((mr + (lane & 15)) * 200 + ((lane >> 4) << 3)) * 2;
    uint32_t a_off1 = a_off0 + 16 * 200 * 2;
    int bn = (lane & 7) + ((lane >> 4) << 3);   // + nc + p*16 -> B row
    int bk = ((lane >> 3) & 1) << 3;            // k half within 16

    // staging map: idx = tid + i*256 in [0,768): n = idx>>2, kq = (idx&3)*8
    int sn = tid >> 2, skq = (tid & 3) * 8;

    // prefetch chunk 0 into buffer 0
#pragma unroll
    for (int i2 = 0; i2 < 3; i2++) {
        int n = sn + i2 * 64;
        cp16(bufu + n * 80 + skq * 2, Wbf + n * DIMC + skq);
    }
    cp_commit();

#pragma unroll 1
    for (int c = 0; c < 6; c++) {
        if (c < 5) {
            const bf16* Wsrc = Wbf + (c + 1) * 32;
            uint32_t dstb = bufu + ((c + 1) & 1) * 15360;
#pragma unroll
            for (int i2 = 0; i2 < 3; i2++) {
                int n = sn + i2 * 64;
                cp16(dstb + n * 80 + skq * 2, Wsrc + n * DIMC + skq);
            }
            cp_commit();
            cp_wait<1>();
        } else {
            cp_wait<0>();
        }
        __syncthreads();
        uint32_t bb = bufu + (c & 1) * 15360;
#pragma unroll
        for (int ks = 0; ks < 2; ks++) {
            int kg = c * 32 + ks * 16;
            uint32_t a0[4], a1[4];
            ldsm4(a0, a_off0 + kg * 2);
            ldsm4(a1, a_off1 + kg * 2);
#pragma unroll
            for (int p = 0; p < 3; p++) {
                uint32_t b[4];
                ldsm4(b, bb + ((nc + p * 16 + bn) * 40 + ks * 16 + bk) * 2);
                mma_bf16(C[0][2 * p],     a0[0], a0[1], a0[2], a0[3], b[0], b[1]);
                mma_bf16(C[1][2 * p],     a1[0], a1[1], a1[2], a1[3], b[0], b[1]);
                mma_bf16(C[0][2 * p + 1], a0[0], a0[1], a0[2], a0[3], b[2], b[3]);
                mma_bf16(C[1][2 * p + 1], a1[0], a1[1], a1[2], a1[3], b[2], b[3]);
            }
        }
        __syncthreads();
    }
}

// ---------------------------------------------------------------------------
// Kernel 2: qkv = (x + pos) @ Wqkv^T, scatter into g_Q/g_K/g_Vt.
// grid (768, 3). smem: As bf16 64x200 (25600B) + stage buffers (30720B).
// ---------------------------------------------------------------------------
__global__ __launch_bounds__(256, 2) void qkv_kernel(const float* __restrict__ x) {
    extern __shared__ char smc[];
    bf16* As  = (bf16*)smc;              // 64*200
    bf16* Buf = (bf16*)(smc + 25600);    // 2 x 192*40

    int tid = threadIdx.x;
    int lane = tid & 31, w = tid >> 5;
    int qr = lane >> 2, qc = lane & 3;
    int r0 = blockIdx.x * 64;
    int s = blockIdx.y;

    // stage A = bf16(x + pos)
#pragma unroll
    for (int q = tid; q < 1536; q += 256) {
        int r = q / 24, c8 = (q % 24) * 8;
        float4 x0 = *(const float4*)(x + (size_t)(r0 + r) * DIMC + c8);
        float4 x1 = *(const float4*)(x + (size_t)(r0 + r) * DIMC + c8 + 4);
        float4 p0 = *(const float4*)(g_pos + r * DIMC + c8);
        float4 p1 = *(const float4*)(g_pos + r * DIMC + c8 + 4);
        uint4 o;
        o.x = packbf(x0.x + p0.x, x0.y + p0.y);
        o.y = packbf(x0.z + p0.z, x0.w + p0.w);
        o.z = packbf(x1.x + p1.x, x1.y + p1.y);
        o.w = packbf(x1.z + p1.z, x1.w + p1.w);
        *(uint4*)(As + r * 200 + c8) = o;
    }
    __syncthreads();

    float C[2][6][4];
#pragma unroll
    for (int a = 0; a < 2; a++)
#pragma unroll
        for (int f = 0; f < 6; f++)
#pragma unroll
            for (int u = 0; u < 4; u++) C[a][f][u] = 0.0f;

    gemm_bf16(As, g_Wqkv + (size_t)s * DIMC * DIMC, Buf, C, tid);

    const float SCALE = 0.17677669529663688f;  // 32^-0.5
    int mr = (w & 1) * 32, nc = (w >> 1) * 48;

    if (s < 2) {
        bf16* GD = (s == 0) ? g_Q : g_K;
        float scl = (s == 0) ? SCALE : 1.0f;
#pragma unroll
        for (int mf = 0; mf < 2; mf++)
#pragma unroll
            for (int f = 0; f < 6; f++) {
                int cg = nc + f * 8 + 2 * qc;
                int h = cg >> 5, d = cg & 31;
#pragma unroll
                for (int half = 0; half < 2; half++) {
                    int gr = r0 + mr + mf * 16 + qr + half * 8;
                    int bidx = gr / NTOK, n = gr % NTOK;
                    int t = n >> 6, hw = n & 63;
                    int dst = ((bidx * NHEAD + h) * TT + t) * 2048 + hw * 32 + d;
                    *(uint32_t*)(GD + dst) =
                        packbf(C[mf][f][half * 2 + 0] * scl, C[mf][f][half * 2 + 1] * scl);
                }
            }
    } else {
        // V transposed: [b][h][t][d][hw]
#pragma unroll
        for (int mf = 0; mf < 2; mf++)
#pragma unroll
            for (int f = 0; f < 6; f++) {
                int cg = nc + f * 8 + 2 * qc;
                int h = cg >> 5, d = cg & 31;
#pragma unroll
                for (int half = 0; half < 2; half++) {
                    int gr = r0 + mr + mf * 16 + qr + half * 8;
                    int bidx = gr / NTOK, n = gr % NTOK;
                    int t = n >> 6, hw = n & 63;
                    int base = ((bidx * NHEAD + h) * TT + t) * 2048;
                    g_Vt[base + d * 64 + hw]       = __float2bfloat16(C[mf][f][half * 2 + 0]);
                    g_Vt[base + (d + 1) * 64 + hw] = __float2bfloat16(C[mf][f][half * 2 + 1]);
                }
            }
    }
}

// ---------------------------------------------------------------------------
// Kernel 2b: XP[i][b] = x_flat @ Wx^T + bproj  (j-invariant), bf16 to g_XP.
// grid (6, 128). smem: As(25600) + Buf(30720).
// ---------------------------------------------------------------------------
__global__ __launch_bounds__(256, 2) void xp_kernel(const float* __restrict__ x,
                                                    const float* __restrict__ bproj) {
    extern __shared__ char smc[];
    bf16* As  = (bf16*)smc;
    bf16* Buf = (bf16*)(smc + 25600);

    int tid = threadIdx.x;
    int lane = tid & 31, w = tid >> 5;
    int qr = lane >> 2, qc = lane & 3;
    int i = blockIdx.x, bb = blockIdx.y;

    size_t Rbase = (size_t)i * 8192 + (size_t)bb * 64;
#pragma unroll
    for (int q = tid; q < 1536; q += 256) {
        int r = q / 24, c8 = (q % 24) * 8;
        float4 x0 = *(const float4*)(x + (Rbase + r) * DIMC + c8);
        float4 x1 = *(const float4*)(x + (Rbase + r) * DIMC + c8 + 4);
        uint4 o;
        o.x = packbf(x0.x, x0.y);
        o.y = packbf(x0.z, x0.w);
        o.z = packbf(x1.x, x1.y);
        o.w = packbf(x1.z, x1.w);
        *(uint4*)(As + r * 200 + c8) = o;
    }
    __syncthreads();

    float C[2][6][4];
#pragma unroll
    for (int a = 0; a < 2; a++)
#pragma unroll
        for (int f = 0; f < 6; f++)
#pragma unroll
            for (int u = 0; u < 4; u++) C[a][f][u] = 0.0f;
    gemm_bf16(As, g_Wx, Buf, C, tid);

    int mr = (w & 1) * 32, nc = (w >> 1) * 48;
    bf16* xp = g_XP + ((size_t)(i * NB + bb) * 64) * DIMC;
#pragma unroll
    for (int mf = 0; mf < 2; mf++)
#pragma unroll
        for (int f = 0; f < 6; f++) {
            int col = nc + f * 8 + 2 * qc;
            float b0v = __ldg(bproj + col), b1v = __ldg(bproj + col + 1);
#pragma unroll
            for (int half = 0; half < 2; half++) {
                int row = mr + mf * 16 + qr + half * 8;
                *(uint32_t*)(xp + row * DIMC + col) =
                    packbf(C[mf][f][half * 2 + 0] + b0v, C[mf][f][half * 2 + 1] + b1v);
            }
        }
}

// ---------------------------------------------------------------------------
// K/V head prefetch: K tile 64x32 -> stride 40; V tile 32x64 -> stride 72.
// ---------------------------------------------------------------------------
__device__ __forceinline__ void issue_kv(const bf16* __restrict__ Kg,
                                         const bf16* __restrict__ Vg,
                                         uint32_t kb, uint32_t vb, int tid) {
    int rk = tid >> 2, sk = (tid & 3) * 8;
    cp16(kb + (rk * 40 + sk) * 2, Kg + rk * 32 + sk);
    int rv = tid >> 3, sv = (tid & 7) * 8;
    cp16(vb + (rv * 72 + sv) * 2, Vg + rv * 64 + sv);
    cp_commit();
}

// ---------------------------------------------------------------------------
// Kernel 3: per-(i, b) fused attention + proj + LN + MLP + j-accumulate + out.
// grid (6, 128), 256 threads, 107520 B dynamic smem -> 2 CTAs/SM.
// ---------------------------------------------------------------------------
__global__ __launch_bounds__(256, 2) void main_kernel(
    const float* __restrict__ x, const float* __restrict__ gamma,
    const float* __restrict__ beta, const float* __restrict__ b1,
    const float* __restrict__ b2, float* __restrict__ out) {
    extern __shared__ char smc[];
    bf16* Qall = (bf16*)smc;                // 64*200 = 25600 B (Q, all heads)
    bf16* Os   = (bf16*)(smc + 25600);      // 64*200
    bf16* Ys   = (bf16*)(smc + 51200);      // 64*200
    // union region @76800 (30720 B): gemm Buf | attention arrays
    bf16*  Buf  = (bf16*)(smc + 76800);     // 2 x 15360 B
    bf16*  Ps   = (bf16*)(smc + 76800);     // 64*72 = 9216 B
    bf16*  Kb   = (bf16*)(smc + 86016);     // 2 x 64*40 = 10240 B
    bf16*  Vb   = (bf16*)(smc + 96256);     // 2 x 32*72 = 9216 B
    float2* stats = (float2*)(smc + 105472);// 64*2 float2 = 1024 B -> end 106496

    int tid = threadIdx.x;
    int lane = tid & 31, w = tid >> 5;
    int qr = lane >> 2, qc = lane & 3;
    int i = blockIdx.x, bb = blockIdx.y;

    int mrG = (w & 1) * 32, ncG = (w >> 1) * 48;   // gemm warp tile
    int mrS = (w & 3) * 16, ncS = (w >> 2) * 32;   // S warp tile (col half)
    int half = w >> 2;                              // which 32-col half of S
    int ncO = (w >> 2) * 16;                       // P@V warp tile

    int bn = (lane & 7) + ((lane >> 4) << 3);
    int bk = ((lane >> 3) & 1) << 3;

    uint32_t kbu = s2u(Kb), vbu = s2u(Vb);
    const bf16* Kbase = g_K  + ((size_t)(bb * NHEAD) * TT << 11);
    const bf16* Vbase = g_Vt + ((size_t)(bb * NHEAD) * TT << 11);

    // prefetch (j=0, h=0) K/V into buffer 0
    issue_kv(Kbase + ((size_t)0 * TT + 0) * 2048, Vbase + ((size_t)0 * TT + 0) * 2048,
             kbu, vbu, tid);

    // ---- stage Q (all 6 heads, this i) into Qall[hw][h*32+d] ----
#pragma unroll
    for (int q = tid; q < 1536; q += 256) {
        int h = q >> 8, r = (q & 255) >> 2, seg = (q & 3) * 8;
        const bf16* Qg = g_Q + ((size_t)((bb * NHEAD + h) * TT + i) << 11);
        *(uint4*)(Qall + r * 200 + h * 32 + seg) = *(const uint4*)(Qg + r * 32 + seg);
    }

    float accF[2][6][4];
#pragma unroll
    for (int a = 0; a < 2; a++)
#pragma unroll
        for (int f = 0; f < 6; f++)
#pragma unroll
            for (int u = 0; u < 4; u++) accF[a][f][u] = 0.0f;
    float accs[2][6][4];

#pragma unroll 1
    for (int j = 0; j < TT; j++) {
        // ---------------- attention: Os[r][h*32+d] ----------------
#pragma unroll 1
        for (int h = 0; h < NHEAD; h++) {
            cp_wait<0>();
            __syncthreads();   // A: K/V[h&1] visible; prior readers of buffers done
            if (h < 5)
                issue_kv(Kbase + ((size_t)(h + 1) * TT + j) * 2048,
                         Vbase + ((size_t)(h + 1) * TT + j) * 2048,
                         kbu + ((h + 1) & 1) * 5120, vbu + ((h + 1) & 1) * 4608, tid);

            // S = Q @ K^T (64x64, K=32), warp tile 16 rows x 32 cols
            float Sc[4][4];
#pragma unroll
            for (int f = 0; f < 4; f++)
#pragma unroll
                for (int u = 0; u < 4; u++) Sc[f][u] = 0.0f;
            {
                uint32_t qbase = s2u(Qall) +
                    ((mrS + (lane & 15)) * 200 + h * 32 + ((lane >> 4) << 3)) * 2;
                uint32_t kbc = kbu + (h & 1) * 5120;
#pragma unroll
                for (int ks = 0; ks < 2; ks++) {
                    uint32_t a[4];
                    ldsm4(a, qbase + ks * 16 * 2);
#pragma unroll
                    for (int p = 0; p < 2; p++) {
                        uint32_t b[4];
                        ldsm4(b, kbc + ((ncS + p * 16 + bn) * 40 + ks * 16 + bk) * 2);
                        mma_bf16(Sc[2 * p],     a[0], a[1], a[2], a[3], b[0], b[1]);
                        mma_bf16(Sc[2 * p + 1], a[0], a[1], a[2], a[3], b[2], b[3]);
                    }
                }
            }

            // register softmax: partial (max,sum) per row over this warp's 32 cols
            float pm[2], psum[2];
#pragma unroll
            for (int r2 = 0; r2 < 2; r2++) {
                float m0 = fmaxf(fmaxf(Sc[0][2 * r2], Sc[0][2 * r2 + 1]),
                                 fmaxf(Sc[1][2 * r2], Sc[1][2 * r2 + 1]));
                float m1 = fmaxf(fmaxf(Sc[2][2 * r2], Sc[2][2 * r2 + 1]),
                                 fmaxf(Sc[3][2 * r2], Sc[3][2 * r2 + 1]));
                float m = fmaxf(m0, m1);
                m = fmaxf(m, __shfl_xor_sync(0xffffffffu, m, 1));
                m = fmaxf(m, __shfl_xor_sync(0xffffffffu, m, 2));
                float s = 0.0f;
#pragma unroll
                for (int f = 0; f < 4; f++) {
                    Sc[f][2 * r2]     = __expf(Sc[f][2 * r2] - m);
                    Sc[f][2 * r2 + 1] = __expf(Sc[f][2 * r2 + 1] - m);
                    s += Sc[f][2 * r2] + Sc[f][2 * r2 + 1];
                }
                s += __shfl_xor_sync(0xffffffffu, s, 1);
                s += __shfl_xor_sync(0xffffffffu, s, 2);
                pm[r2] = m; psum[r2] = s;
            }
            if (qc == 0) {
                stats[(mrS + qr) * 2 + half]     = make_float2(pm[0], psum[0]);
                stats[(mrS + qr + 8) * 2 + half] = make_float2(pm[1], psum[1]);
            }
            __syncthreads();   // B

            // combine halves, normalize, write P bf16
#pragma unroll
            for (int r2 = 0; r2 < 2; r2++) {
                int row = mrS + qr + r2 * 8;
                float2 o0 = stats[row * 2 + 0];
                float2 o1 = stats[row * 2 + 1];
                float mm = fmaxf(o0.x, o1.x);
                float stot = o0.y * __expf(o0.x - mm) + o1.y * __expf(o1.x - mm);
                float scale = __expf(pm[r2] - mm) / stot;
#pragma unroll
                for (int f = 0; f < 4; f++) {
                    *(uint32_t*)(Ps + row * 72 + ncS + f * 8 + 2 * qc) =
                        packbf(Sc[f][2 * r2] * scale, Sc[f][2 * r2 + 1] * scale);
                }
            }
            __syncthreads();   // C

            // O = P @ V^T (64x32, K=64), warp tile 16 rows x 16 d; Vb is [d][hw]
            {
                float Oc[2][4];
#pragma unroll
                for (int f = 0; f < 2; f++)
#pragma unroll
                    for (int u = 0; u < 4; u++) Oc[f][u] = 0.0f;
                uint32_t pbase = s2u(Ps) +
                    ((mrS + (lane & 15)) * 72 + ((lane >> 4) << 3)) * 2;
                uint32_t vbc = vbu + (h & 1) * 4608;
#pragma unroll
                for (int ks = 0; ks < 4; ks++) {
                    uint32_t a[4], b[4];
                    ldsm4(a, pbase + ks * 16 * 2);
                    ldsm4(b, vbc + ((ncO + bn) * 72 + ks * 16 + bk) * 2);
                    mma_bf16(Oc[0], a[0], a[1], a[2], a[3], b[0], b[1]);
                    mma_bf16(Oc[1], a[0], a[1], a[2], a[3], b[2], b[3]);
                }
#pragma unroll
                for (int f = 0; f < 2; f++) {
                    int col = h * 32 + ncO + f * 8 + 2 * qc;
                    *(uint32_t*)(Os + (mrS + qr) * 200 + col)     = packbf(Oc[f][0], Oc[f][1]);
                    *(uint32_t*)(Os + (mrS + qr + 8) * 200 + col) = packbf(Oc[f][2], Oc[f][3]);
                }
            }
            // no trailing sync: next head's barrier A covers
        }
        __syncthreads();   // protect Ps/Kb/Vb (aliased by gemm Buf) + Os reads

        // ---------------- y = Os @ Wo^T + XP(global) ----------------
#pragma unroll
        for (int a = 0; a < 2; a++)
#pragma unroll
            for (int f = 0; f < 6; f++)
#pragma unroll
                for (int u = 0; u < 4; u++) accs[a][f][u] = 0.0f;
        gemm_bf16(Os, g_Wo, Buf, accs, tid);
        {
            const bf16* xp = g_XP + ((size_t)(i * NB + bb) * 64) * DIMC;
#pragma unroll
            for (int mf = 0; mf < 2; mf++)
#pragma unroll
                for (int f = 0; f < 6; f++) {
                    int col = ncG + f * 8 + 2 * qc;
#pragma unroll
                    for (int hf = 0; hf < 2; hf++) {
                        int row = mrG + mf * 16 + qr + hf * 8;
                        float2 xv = unpackbf(*(const uint32_t*)(xp + row * DIMC + col));
                        *(uint32_t*)(Ys + row * 200 + col) =
                            packbf(accs[mf][f][hf * 2 + 0] + xv.x,
                                   accs[mf][f][hf * 2 + 1] + xv.y);
                    }
                }
        }
        __syncthreads();

        // ---------------- LayerNorm rows of Ys ----------------
#pragma unroll
        for (int rr = 0; rr < 8; rr++) {
            int row = w * 8 + rr;
            float2 vv[3];
            float s1 = 0.0f, s2 = 0.0f;
#pragma unroll
            for (int u = 0; u < 3; u++) {
                vv[u] = unpackbf(*(const uint32_t*)(Ys + row * 200 + 2 * lane + 64 * u));
                s1 += vv[u].x + vv[u].y;
                s2 += vv[u].x * vv[u].x + vv[u].y * vv[u].y;
            }
#pragma unroll
            for (int off = 16; off; off >>= 1) {
                s1 += __shfl_xor_sync(0xffffffffu, s1, off);
                s2 += __shfl_xor_sync(0xffffffffu, s2, off);
            }
            float mu = s1 * (1.0f / 192.0f);
            float var = s2 * (1.0f / 192.0f) - mu * mu;
            float rstd = rsqrtf(var + 1e-5f);
#pragma unroll
            for (int u = 0; u < 3; u++) {
                int c = 2 * lane + 64 * u;
                float y0 = (vv[u].x - mu) * rstd * __ldg(gamma + c)     + __ldg(beta + c);
                float y1 = (vv[u].y - mu) * rstd * __ldg(gamma + c + 1) + __ldg(beta + c + 1);
                *(uint32_t*)(Ys + row * 200 + c) = packbf(y0, y1);
            }
        }
        __syncthreads();

        // ---------------- Os = gelu(Ys @ W1^T + b1) ----------------
#pragma unroll
        for (int a = 0; a < 2; a++)
#pragma unroll
            for (int f = 0; f < 6; f++)
#pragma unroll
                for (int u = 0; u < 4; u++) accs[a][f][u] = 0.0f;
        gemm_bf16(Ys, g_W1b, Buf, accs, tid);
#pragma unroll
        for (int mf = 0; mf < 2; mf++)
#pragma unroll
            for (int f = 0; f < 6; f++) {
                int col = ncG + f * 8 + 2 * qc;
                float b0v = __ldg(b1 + col), b1v = __ldg(b1 + col + 1);
#pragma unroll
                for (int hf = 0; hf < 2; hf++) {
                    int row = mrG + mf * 16 + qr + hf * 8;
                    float h0 = accs[mf][f][hf * 2 + 0] + b0v;
                    float h1 = accs[mf][f][hf * 2 + 1] + b1v;
                    float g0 = 0.5f * h0 * (1.0f + erff(h0 * 0.70710678118654752f));
                    float g1 = 0.5f * h1 * (1.0f + erff(h1 * 0.70710678118654752f));
                    *(uint32_t*)(Os + row * 200 + col) = packbf(g0, g1);
                }
            }
        __syncthreads();

        // ---------------- accF += Os @ W2^T ----------------
        gemm_bf16(Os, g_W2b, Buf, accF, tid);
        // gemm ends with cp_wait<0> + __syncthreads -> safe to prefetch K/V
        if (j < 5)
            issue_kv(Kbase + ((size_t)0 * TT + j + 1) * 2048,
                     Vbase + ((size_t)0 * TT + j + 1) * 2048, kbu, vbu, tid);
    }

    // ---------------- write out: [x | x + acc/T + b2] ----------------
#pragma unroll
    for (int mf = 0; mf < 2; mf++)
#pragma unroll
        for (int f = 0; f < 6; f++) {
            int col = ncG + f * 8 + 2 * qc;
            float b20 = __ldg(b2 + col), b21 = __ldg(b2 + col + 1);
#pragma unroll
            for (int hf = 0; hf < 2; hf++) {
                int row = mrG + mf * 16 + qr + hf * 8;
                int n = i * 64 + row;
                size_t base = (size_t)bb * NTOK + n;
                float2 xv = *(const float2*)(x + base * DIMC + col);
                *(float2*)(out + base * (2 * DIMC) + col) = xv;
                float2 ov;
                ov.x = xv.x + accF[mf][f][hf * 2 + 0] * (1.0f / 6.0f) + b20;
                ov.y = xv.y + accF[mf][f][hf * 2 + 1] * (1.0f / 6.0f) + b21;
                *(float2*)(out + base * (2 * DIMC) + DIMC + col) = ov;
            }
        }
}

// ---------------------------------------------------------------------------
extern "C" void kernel_launch(void* const* d_in, const int* in_sizes, int n_in,
                              void* d_out, int out_size) {
    (void)in_sizes; (void)n_in; (void)out_size;
    const float* x     = (const float*)d_in[0];
    const float* Wqkv  = (const float*)d_in[1];
    const float* Wproj = (const float*)d_in[2];
    const float* bproj = (const float*)d_in[3];
    const float* gamma = (const float*)d_in[4];
    const float* beta  = (const float*)d_in[5];
    const float* W1    = (const float*)d_in[6];
    const float* b1    = (const float*)d_in[7];
    const float* W2    = (const float*)d_in[8];
    const float* b2    = (const float*)d_in[9];
    float* out = (float*)d_out;

    prep_kernel<<<432, 256>>>(Wqkv, Wproj, W1, W2);
    pos_kernel<<<48, 256>>>();

    const int gsmem = 25600 + 30720;  // 56320 B
    cudaFuncSetAttribute(xp_kernel, cudaFuncAttributeMaxDynamicSharedMemorySize, gsmem);
    xp_kernel<<<dim3(TT, NB), 256, gsmem>>>(x, bproj);
    cudaFuncSetAttribute(qkv_kernel, cudaFuncAttributeMaxDynamicSharedMemorySize, gsmem);
    qkv_kernel<<<dim3(768, 3), 256, gsmem>>>(x);

    const int main_smem = 107520;
    cudaFuncSetAttribute(main_kernel, cudaFuncAttributeMaxDynamicSharedMemorySize, main_smem);
    main_kernel<<<dim3(TT, NB), 256, main_smem>>>(x, gamma, beta, b1, b2, out);
}